// round 2
// baseline (speedup 1.0000x reference)
#include <cuda_runtime.h>
#include <cstdint>

// Problem constants
#define NGRAPH 512
#define NPG    125
#define D      128
#define SH     69           // S_HID
#define NC     10           // clusters
#define HS_LD  129          // padded H row stride (conflict-free col walks)
#define AS_LD  81           // padded A row stride (odd -> conflict-free in stage Z)

// d_out float offsets (outputs concatenated in return order)
#define P1_OFF  0
#define P2_OFF  1024
#define IND_OFF 2048
#define S_OFF   2560
#define E_OFF   642560
#define Q_OFF   1297920

// Shared-memory layout (float offsets)
#define HS_OFF   0           // [128][129] = 16512 floats (rows 125..127 zeroed)
#define REG_OFF  16512       // W1 pairs [128][40] f2 (10240 f) / As [128][81] (10368 f)
#define W2_OFF   26880       // [69][10] = 690
#define SS_OFF   27570       // [125][10] = 1250
#define B1_OFF   28820       // [80]
#define SM_FLOATS 28900      // 115,600 bytes

// k2 temporaries aliased into the REG region (dead after stage Z / reused)
#define ES_OFF   16512       // 1280
#define P1S_OFF  17792       // 1024
#define P2S_OFF  18816       // 128
#define TS_OFF   18944       // 80
#define QR_OFF   19024       // 160
#define FM_OFF   19184       // 10
#define RED_OFF  19200       // 16
#define SC_OFF   19216       // 2
#define CORR_OFF 19224       // 32
#define CM_OFF   19256       // 16

// ---------------------------------------------------------------------------
// Packed f32x2 helpers (Blackwell dual fp32 path; ptxas never emits these)
// ---------------------------------------------------------------------------
__device__ __forceinline__ unsigned long long pk2(float a, float b) {
    unsigned long long r;
    asm("mov.b64 %0,{%1,%2};" : "=l"(r) : "f"(a), "f"(b));
    return r;
}
__device__ __forceinline__ void upk2(unsigned long long p, float& a, float& b) {
    asm("mov.b64 {%0,%1},%2;" : "=f"(a), "=f"(b) : "l"(p));
}
__device__ __forceinline__ void fma2(unsigned long long& d,
                                     unsigned long long a, unsigned long long b) {
    asm("fma.rn.f32x2 %0,%1,%2,%3;" : "=l"(d) : "l"(a), "l"(b), "l"(d));
}

// ---------------------------------------------------------------------------
// Threefry-2x32 (JAX partitionable path) — verified bit-exact in R1
// ---------------------------------------------------------------------------
__device__ __forceinline__ void threefry2x32(uint32_t k0, uint32_t k1,
                                             uint32_t c0, uint32_t c1,
                                             uint32_t& y0, uint32_t& y1)
{
    uint32_t ks2 = k0 ^ k1 ^ 0x1BD11BDAu;
    uint32_t x0 = c0 + k0, x1 = c1 + k1;
#define TF_RND(r) { x0 += x1; x1 = (x1 << (r)) | (x1 >> (32 - (r))); x1 ^= x0; }
    TF_RND(13) TF_RND(15) TF_RND(26) TF_RND(6)  x0 += k1;  x1 += ks2 + 1u;
    TF_RND(17) TF_RND(29) TF_RND(16) TF_RND(24) x0 += ks2; x1 += k0  + 2u;
    TF_RND(13) TF_RND(15) TF_RND(26) TF_RND(6)  x0 += k0;  x1 += k1  + 3u;
    TF_RND(17) TF_RND(29) TF_RND(16) TF_RND(24) x0 += k1;  x1 += ks2 + 4u;
    TF_RND(13) TF_RND(15) TF_RND(26) TF_RND(6)  x0 += ks2; x1 += k0  + 5u;
#undef TF_RND
    y0 = x0; y1 = x1;
}
__device__ __forceinline__ float jax_unit_uniform(uint32_t f)
{
    uint32_t y0, y1;
    threefry2x32(0u, 42u, 0u, f, y0, y1);
    uint32_t bits = y0 ^ y1;
    float v = __uint_as_float((bits >> 9) | 0x3f800000u) - 1.0f;
    return (v == 0.0f) ? 1.17549435e-38f : v;
}

// ---------------------------------------------------------------------------
// Fully fused kernel: one block per graph, 256 threads.
// ---------------------------------------------------------------------------
__global__ __launch_bounds__(256, 2) void ciflow_fused(
    const float* __restrict__ H,
    const int*   __restrict__ targets,
    const float* __restrict__ w1,  const float* __restrict__ b1,
    const float* __restrict__ w2,  const float* __restrict__ b2,
    const float* __restrict__ wf,  const float* __restrict__ bf,
    const float* __restrict__ p1,  const float* __restrict__ pb1,
    const float* __restrict__ p2,  const float* __restrict__ pb2,
    const float* __restrict__ ci,  const float* __restrict__ cia,
    float* __restrict__ out)
{
    extern __shared__ float sm[];
    float*  Hs  = sm + HS_OFF;
    float2* W1p = (float2*)(sm + REG_OFF);   // [128][40] column pairs
    float*  As  = sm + REG_OFF;              // [128][81] (aliases W1p after stage A)
    float*  W2s = sm + W2_OFF;
    float*  Ss  = sm + SS_OFF;
    float*  b1s = sm + B1_OFF;

    const int g    = blockIdx.x;
    const int tid  = threadIdx.x;
    const int lane = tid & 31;
    const int wid  = tid >> 5;
    const int tx   = tid & 31;   // M: rows tx + 32*i
    const int ty   = tid >> 5;   // N: col pairs 5*ty + q  (cols 10*ty + 2q + {0,1})

    // ---- cooperative loads --------------------------------------------------
    const float* Hg = H + (size_t)g * NPG * D;
    for (int idx = tid; idx < NPG * D; idx += 256) {
        int m = idx >> 7, k = idx & 127;
        Hs[m * HS_LD + k] = Hg[idx];
    }
    for (int idx = tid; idx < 3 * HS_LD; idx += 256)
        Hs[NPG * HS_LD + idx] = 0.0f;                       // zero rows 125..127
    for (int idx = tid; idx < 128 * 40; idx += 256) {       // W1 as column pairs
        int k = idx / 40, pr = idx - k * 40;
        int c0 = 2 * pr;
        float lo = (c0     < SH) ? w1[k * SH + c0]     : 0.0f;
        float hi = (c0 + 1 < SH) ? w1[k * SH + c0 + 1] : 0.0f;
        W1p[idx] = make_float2(lo, hi);
    }
    for (int idx = tid; idx < SH * NC; idx += 256) W2s[idx] = w2[idx];
    if (tid < 80) b1s[tid] = (tid < SH) ? b1[tid] : 0.0f;
    __syncthreads();

    // ---- stage A: A = relu(H @ w1 + b1), packed f32x2 -----------------------
    unsigned long long acc[4][5];
#pragma unroll
    for (int i = 0; i < 4; ++i)
#pragma unroll
        for (int q = 0; q < 5; ++q) acc[i][q] = 0ull;

    const unsigned long long* W1row =
        (const unsigned long long*)(W1p) + 5 * ty;
#pragma unroll 2
    for (int k = 0; k < 128; ++k) {
        unsigned long long hp[4];
#pragma unroll
        for (int i = 0; i < 4; ++i) {
            float h = Hs[(tx + 32 * i) * HS_LD + k];
            hp[i] = pk2(h, h);
        }
        unsigned long long wp[5];
#pragma unroll
        for (int q = 0; q < 5; ++q) wp[q] = W1row[k * 40 + q];
#pragma unroll
        for (int i = 0; i < 4; ++i)
#pragma unroll
            for (int q = 0; q < 5; ++q) fma2(acc[i][q], hp[i], wp[q]);
    }
    __syncthreads();            // all W1p reads done before aliasing to As
#pragma unroll
    for (int i = 0; i < 4; ++i) {
        int m = tx + 32 * i;
#pragma unroll
        for (int q = 0; q < 5; ++q) {
            float lo, hi;
            upk2(acc[i][q], lo, hi);
            int c = 10 * ty + 2 * q;
            As[m * AS_LD + c    ] = fmaxf(lo + b1s[c    ], 0.0f);
            As[m * AS_LD + c + 1] = fmaxf(hi + b1s[c + 1], 0.0f);
        }
    }
    __syncthreads();

    // ---- stage Z: z = A @ w2 + b2, softmax -> S (2 threads per row) ---------
    {
        const int m    = tid >> 1;
        const int half = tid & 1;
        const int cb   = 5 * half;
        float z[5];
#pragma unroll
        for (int c = 0; c < 5; ++c) z[c] = __ldg(&b2[cb + c]);
        for (int n = 0; n < SH; ++n) {
            float a = As[m * AS_LD + n];
#pragma unroll
            for (int c = 0; c < 5; ++c) z[c] = fmaf(a, W2s[n * NC + cb + c], z[c]);
        }
        float mx = z[0];
#pragma unroll
        for (int c = 1; c < 5; ++c) mx = fmaxf(mx, z[c]);
        mx = fmaxf(mx, __shfl_xor_sync(0xffffffffu, mx, 1));
        float ssum = 0.0f;
#pragma unroll
        for (int c = 0; c < 5; ++c) { z[c] = expf(z[c] - mx); ssum += z[c]; }
        ssum += __shfl_xor_sync(0xffffffffu, ssum, 1);
        float inv = 1.0f / ssum;
        if (m < NPG) {
            float* srow = &Ss[m * NC + cb];
            float* gout = out + S_OFF + ((size_t)g * NPG + m) * NC + cb;
#pragma unroll
            for (int c = 0; c < 5; ++c) {
                float s = z[c] * inv;
                srow[c] = s;
                gout[c] = s;
            }
        }
    }
    __syncthreads();

    // ---- stage E: E[c][d] = sum_m S[m][c] H[m][d] ---------------------------
    // (also prefetch p1/p2 into the dead part of the REG region)
    float* Es  = sm + ES_OFF;
    float* p1s = sm + P1S_OFF;
    float* p2s = sm + P2S_OFF;
    {
        // prefetch (overlaps with E compute below via MLP)
        float pf[4];
#pragma unroll
        for (int r = 0; r < 4; ++r) pf[r] = __ldg(&p1[tid + 256 * r]);
        float pf2 = (tid < 128) ? __ldg(&p2[tid]) : 0.0f;

        const int d  = tid & 127;
        const int c0 = (tid >> 7) * 5;
        float e[5] = {0.f, 0.f, 0.f, 0.f, 0.f};
        for (int m = 0; m < NPG; ++m) {
            float h = Hs[m * HS_LD + d];
#pragma unroll
            for (int j = 0; j < 5; ++j) e[j] = fmaf(Ss[m * NC + c0 + j], h, e[j]);
        }
        float* Eout = out + E_OFF + (size_t)g * (NC * D);
#pragma unroll
        for (int j = 0; j < 5; ++j) {
            Eout[(c0 + j) * D + d] = e[j];
            Es[(c0 + j) * D + d]   = e[j];     // REG region rows 0..9 (dead As)
        }
#pragma unroll
        for (int r = 0; r < 4; ++r) p1s[tid + 256 * r] = pf[r];
        if (tid < 128) p2s[tid] = pf2;
    }
    __syncthreads();

    // ======================= fused downstream (old k2) =======================
    float* ts    = sm + TS_OFF;
    float* qraw  = sm + QR_OFF;
    float* fms   = sm + FM_OFF;
    float* red   = sm + RED_OFF;
    float* sc    = sm + SC_OFF;
    float* corrs = sm + CORR_OFF;
    float* cmask = sm + CM_OFF;

    // ---- pred1 (wf streamed from L2) ---------------------------------------
    float s0 = 0.f, s1 = 0.f;
#pragma unroll
    for (int r = 0; r < 5; ++r) {
        int i = tid + 256 * r;
        float e = Es[i];
        float2 w = __ldg((const float2*)(wf + 2 * i));
        s0 = fmaf(e, w.x, s0);
        s1 = fmaf(e, w.y, s1);
    }
#pragma unroll
    for (int off = 16; off; off >>= 1) {
        s0 += __shfl_down_sync(0xffffffffu, s0, off);
        s1 += __shfl_down_sync(0xffffffffu, s1, off);
    }
    if (lane == 0) { red[wid * 2] = s0; red[wid * 2 + 1] = s1; }
    __syncthreads();

    if (tid == 0) {
        float z0 = bf[0], z1 = bf[1];
#pragma unroll
        for (int w = 0; w < 8; ++w) { z0 += red[2 * w]; z1 += red[2 * w + 1]; }
        out[P1_OFF + g * 2 + 0] = z0;
        out[P1_OFF + g * 2 + 1] = z1;
        float mx = fmaxf(z0, z1);
        float e0 = expf(z0 - mx), e1 = expf(z1 - mx);
        float inv = 1.0f / (e0 + e1);
        float pp0 = e0 * inv, pp1 = e1 * inv;

        float u0 = jax_unit_uniform(2u * g);
        float u1 = jax_unit_uniform(2u * g + 1u);
        float l0 = logf(pp0 + 1e-12f) - logf(-logf(u0));
        float l1 = logf(pp1 + 1e-12f) - logf(-logf(u1));
        int sample = (l1 > l0) ? 1 : 0;

        out[IND_OFF + g] = (sample == targets[g]) ? 1.0f : 0.0f;
        sc[0] = pp0 + ((sample == 0) ? (1.0f - pp0) : -pp0);
        sc[1] = pp1 + ((sample == 1) ? (1.0f - pp1) : -pp1);
    }

    // correlation = softmax(ci, axis=0) * softmax(cia, axis=1)   [2,16]
    if (tid >= 32 && tid < 64) {
        int t = tid - 32;
        int c = t >> 4, f = t & 15;
        float a0 = __ldg(&ci[f]), a1 = __ldg(&ci[16 + f]);
        float m = fmaxf(a0, a1);
        float e0 = expf(a0 - m), e1 = expf(a1 - m);
        float colv = ((c == 0) ? e0 : e1) / (e0 + e1);
        float rm = -1e30f;
        for (int ff = 0; ff < 16; ++ff) rm = fmaxf(rm, __ldg(&cia[c * 16 + ff]));
        float rs = 0.f;
        for (int ff = 0; ff < 16; ++ff) rs += expf(__ldg(&cia[c * 16 + ff]) - rm);
        corrs[c * 16 + f] = colv * (expf(__ldg(&cia[c * 16 + f]) - rm) / rs);
    }

    // ---- Q hidden layer: t = relu(E @ p1 + pb1)  [10][8] --------------------
    if (tid >= 64 && tid < 144) {
        int t = tid - 64;
        int c = t >> 3, j = t & 7;
        float a = __ldg(&pb1[j]);
        for (int k = 0; k < 128; ++k)
            a = fmaf(Es[c * 128 + k], p1s[k * 8 + j], a);
        ts[t] = fmaxf(a, 0.0f);
    }
    __syncthreads();

    if (tid < 16) cmask[tid] = sc[0] * corrs[tid] + sc[1] * corrs[16 + tid];

    // ---- Q output layer  [10][16] -------------------------------------------
    if (tid < 160) {
        int c = tid >> 4, f = tid & 15;
        float a = __ldg(&pb2[f]);
#pragma unroll
        for (int j = 0; j < 8; ++j) a = fmaf(ts[c * 8 + j], p2s[j * 16 + f], a);
        qraw[tid] = a;
    }
    __syncthreads();

    if (tid < NC) {
        int c = tid;
        float mx = -1e30f;
        for (int f = 0; f < 16; ++f) mx = fmaxf(mx, qraw[c * 16 + f]);
        float ssum = 0.f;
        for (int f = 0; f < 16; ++f) ssum += expf(qraw[c * 16 + f] - mx);
        float inv = 1.0f / ssum;
        float fm = 0.f;
        float* qout = out + Q_OFF + (size_t)g * 160 + c * 16;
        for (int f = 0; f < 16; ++f) {
            float q = expf(qraw[c * 16 + f] - mx) * inv;
            qout[f] = q;
            fm = fmaf(q, cmask[f], fm);
        }
        fms[c] = fm;
    }
    __syncthreads();

    // ---- pred2 --------------------------------------------------------------
    s0 = 0.f; s1 = 0.f;
#pragma unroll
    for (int r = 0; r < 5; ++r) {
        int i = tid + 256 * r;
        float e = fms[i >> 7] * Es[i];
        float2 w = __ldg((const float2*)(wf + 2 * i));
        s0 = fmaf(e, w.x, s0);
        s1 = fmaf(e, w.y, s1);
    }
#pragma unroll
    for (int off = 16; off; off >>= 1) {
        s0 += __shfl_down_sync(0xffffffffu, s0, off);
        s1 += __shfl_down_sync(0xffffffffu, s1, off);
    }
    if (lane == 0) { red[wid * 2] = s0; red[wid * 2 + 1] = s1; }
    __syncthreads();
    if (tid == 0) {
        float z0 = bf[0], z1 = bf[1];
#pragma unroll
        for (int w = 0; w < 8; ++w) { z0 += red[2 * w]; z1 += red[2 * w + 1]; }
        out[P2_OFF + g * 2 + 0] = z0;
        out[P2_OFF + g * 2 + 1] = z1;
    }
}

// ---------------------------------------------------------------------------
extern "C" void kernel_launch(void* const* d_in, const int* in_sizes, int n_in,
                              void* d_out, int out_size)
{
    const float* H   = (const float*)d_in[0];
    const int*   tgt = (const int*)  d_in[2];
    const float* w1  = (const float*)d_in[3];
    const float* b1  = (const float*)d_in[4];
    const float* w2  = (const float*)d_in[5];
    const float* b2  = (const float*)d_in[6];
    const float* wf  = (const float*)d_in[7];
    const float* bf  = (const float*)d_in[8];
    const float* p1  = (const float*)d_in[9];
    const float* pb1 = (const float*)d_in[10];
    const float* p2  = (const float*)d_in[11];
    const float* pb2 = (const float*)d_in[12];
    const float* ci  = (const float*)d_in[13];
    const float* cia = (const float*)d_in[14];
    float* out = (float*)d_out;

    const int smem = SM_FLOATS * 4;
    static bool attr_set = false;
    if (!attr_set) {
        cudaFuncSetAttribute(ciflow_fused,
                             cudaFuncAttributeMaxDynamicSharedMemorySize, smem);
        attr_set = true;
    }

    ciflow_fused<<<NGRAPH, 256, smem>>>(H, tgt, w1, b1, w2, b2, wf, bf,
                                        p1, pb1, p2, pb2, ci, cia, out);
}

// round 3
// speedup vs baseline: 1.1225x; 1.1225x over previous
#include <cuda_runtime.h>
#include <cstdint>

// Problem constants
#define NGRAPH 512
#define NPG    125
#define D      128
#define SH     69           // S_HID
#define SHP    80           // padded S_HID
#define NC     10           // clusters
#define HS_LD  129          // padded H row stride (conflict-free col walks)
#define AS_LD  81           // padded A row stride

// d_out float offsets (outputs concatenated in return order)
#define P1_OFF  0
#define P2_OFF  1024
#define IND_OFF 2048
#define S_OFF   2560
#define E_OFF   642560
#define Q_OFF   1297920

// Shared-memory layout (float offsets)
#define HS_OFF   0           // [128][129] (rows 125..127 zeroed)
#define REG_OFF  16512       // W1 [128][80] (10240 f) / As [128][81] (10368 f)
#define W2_OFF   26880       // [69][10] = 690
#define SS_OFF   27570       // [125][10] = 1250
#define B1_OFF   28820       // [80]
#define SM_FLOATS 28900      // 115,600 bytes

// tail temporaries aliased into the REG region (dead after stage Z)
#define ES_OFF   16512       // 1280
#define P1S_OFF  17792       // 1024
#define P2S_OFF  18816       // 128
#define TS_OFF   18944       // 80
#define QR_OFF   19024       // 160
#define FM_OFF   19184       // 10
#define RED_OFF  19200       // 32
#define SC_OFF   19232       // 2
#define CORR_OFF 19240       // 32
#define CM_OFF   19272       // 16

// ---------------------------------------------------------------------------
// Threefry-2x32 (JAX partitionable path) — verified bit-exact in R1/R2
// ---------------------------------------------------------------------------
__device__ __forceinline__ void threefry2x32(uint32_t k0, uint32_t k1,
                                             uint32_t c0, uint32_t c1,
                                             uint32_t& y0, uint32_t& y1)
{
    uint32_t ks2 = k0 ^ k1 ^ 0x1BD11BDAu;
    uint32_t x0 = c0 + k0, x1 = c1 + k1;
#define TF_RND(r) { x0 += x1; x1 = (x1 << (r)) | (x1 >> (32 - (r))); x1 ^= x0; }
    TF_RND(13) TF_RND(15) TF_RND(26) TF_RND(6)  x0 += k1;  x1 += ks2 + 1u;
    TF_RND(17) TF_RND(29) TF_RND(16) TF_RND(24) x0 += ks2; x1 += k0  + 2u;
    TF_RND(13) TF_RND(15) TF_RND(26) TF_RND(6)  x0 += k0;  x1 += k1  + 3u;
    TF_RND(17) TF_RND(29) TF_RND(16) TF_RND(24) x0 += k1;  x1 += ks2 + 4u;
    TF_RND(13) TF_RND(15) TF_RND(26) TF_RND(6)  x0 += ks2; x1 += k0  + 5u;
#undef TF_RND
    y0 = x0; y1 = x1;
}
__device__ __forceinline__ float jax_unit_uniform(uint32_t f)
{
    uint32_t y0, y1;
    threefry2x32(0u, 42u, 0u, f, y0, y1);
    uint32_t bits = y0 ^ y1;
    float v = __uint_as_float((bits >> 9) | 0x3f800000u) - 1.0f;
    return (v == 0.0f) ? 1.17549435e-38f : v;
}

// ---------------------------------------------------------------------------
// Fully fused kernel: one block per graph, 512 threads.
// ---------------------------------------------------------------------------
__global__ __launch_bounds__(512, 1) void ciflow_fused(
    const float* __restrict__ H,
    const int*   __restrict__ targets,
    const float* __restrict__ w1,  const float* __restrict__ b1,
    const float* __restrict__ w2,  const float* __restrict__ b2,
    const float* __restrict__ wf,  const float* __restrict__ bf,
    const float* __restrict__ p1,  const float* __restrict__ pb1,
    const float* __restrict__ p2,  const float* __restrict__ pb2,
    const float* __restrict__ ci,  const float* __restrict__ cia,
    float* __restrict__ out)
{
    extern __shared__ float sm[];
    float* Hs  = sm + HS_OFF;
    float* W1s = sm + REG_OFF;   // [128][80]
    float* As  = sm + REG_OFF;   // [128][81] (aliases W1s after stage A)
    float* W2s = sm + W2_OFF;
    float* Ss  = sm + SS_OFF;
    float* b1s = sm + B1_OFF;

    const int g    = blockIdx.x;
    const int tid  = threadIdx.x;
    const int lane = tid & 31;
    const int wid  = tid >> 5;

    // ---- cooperative loads --------------------------------------------------
    const float* Hg = H + (size_t)g * NPG * D;
    for (int idx = tid; idx < NPG * D; idx += 512) {
        int m = idx >> 7, k = idx & 127;
        Hs[m * HS_LD + k] = Hg[idx];
    }
    for (int idx = tid; idx < 3 * HS_LD; idx += 512)
        Hs[NPG * HS_LD + idx] = 0.0f;                       // zero rows 125..127
    for (int idx = tid; idx < 128 * SHP; idx += 512) {
        int k = idx / SHP, n = idx - k * SHP;
        W1s[idx] = (n < SH) ? w1[k * SH + n] : 0.0f;
    }
    for (int idx = tid; idx < SH * NC; idx += 512) W2s[idx] = w2[idx];
    if (tid < SHP) b1s[tid] = (tid < SH) ? b1[tid] : 0.0f;
    __syncthreads();

    // ---- stage A: A = relu(H @ w1 + b1) -------------------------------------
    // 32 tx (M) x 16 ty (N): each thread 4 rows (tx+32i) x 5 cols (ty+16j).
    // W loads broadcast within warp (all lanes share ty); H loads conflict-free.
    const int tx = tid & 31;
    const int ty = tid >> 5;
    float acc[4][5];
#pragma unroll
    for (int i = 0; i < 4; ++i)
#pragma unroll
        for (int j = 0; j < 5; ++j) acc[i][j] = 0.0f;

#pragma unroll 2
    for (int k = 0; k < 128; ++k) {
        float h[4], w[5];
#pragma unroll
        for (int i = 0; i < 4; ++i) h[i] = Hs[(tx + 32 * i) * HS_LD + k];
#pragma unroll
        for (int j = 0; j < 5; ++j) w[j] = W1s[k * SHP + ty + 16 * j];
#pragma unroll
        for (int i = 0; i < 4; ++i)
#pragma unroll
            for (int j = 0; j < 5; ++j) acc[i][j] = fmaf(h[i], w[j], acc[i][j]);
    }
    __syncthreads();            // all W1s reads done before aliasing to As
#pragma unroll
    for (int i = 0; i < 4; ++i) {
        int m = tx + 32 * i;
#pragma unroll
        for (int j = 0; j < 5; ++j) {
            int n = ty + 16 * j;
            As[m * AS_LD + n] = fmaxf(acc[i][j] + b1s[n], 0.0f);
        }
    }
    __syncthreads();

    // ---- stage Z: z = A @ w2 + b2, softmax -> S (2 threads per row) ---------
    if (tid < 256) {
        const int m    = tid >> 1;
        const int half = tid & 1;
        const int cb   = 5 * half;
        float z[5];
#pragma unroll
        for (int c = 0; c < 5; ++c) z[c] = __ldg(&b2[cb + c]);
        for (int n = 0; n < SH; ++n) {
            float a = As[m * AS_LD + n];
#pragma unroll
            for (int c = 0; c < 5; ++c) z[c] = fmaf(a, W2s[n * NC + cb + c], z[c]);
        }
        float mx = z[0];
#pragma unroll
        for (int c = 1; c < 5; ++c) mx = fmaxf(mx, z[c]);
        mx = fmaxf(mx, __shfl_xor_sync(0xffffffffu, mx, 1));
        float ssum = 0.0f;
#pragma unroll
        for (int c = 0; c < 5; ++c) { z[c] = expf(z[c] - mx); ssum += z[c]; }
        ssum += __shfl_xor_sync(0xffffffffu, ssum, 1);
        float inv = 1.0f / ssum;
        if (m < NPG) {
            float* srow = &Ss[m * NC + cb];
            float* gout = out + S_OFF + ((size_t)g * NPG + m) * NC + cb;
#pragma unroll
            for (int c = 0; c < 5; ++c) {
                float s = z[c] * inv;
                srow[c] = s;
                gout[c] = s;
            }
        }
    }
    __syncthreads();

    // ---- stage E: E[c][d] = sum_m S[m][c] H[m][d], 512 threads --------------
    // c-groups per (tid>>7): starts {0,3,6,8}, counts {3,3,2,2}
    float* Es  = sm + ES_OFF;
    float* p1s = sm + P1S_OFF;
    float* p2s = sm + P2S_OFF;
    {
        // prefetch p1/p2 (lands after E compute, overlapped via MLP)
        float pf[2];
#pragma unroll
        for (int r = 0; r < 2; ++r) pf[r] = __ldg(&p1[tid + 512 * r]);
        float pf2 = (tid < 128) ? __ldg(&p2[tid]) : 0.0f;

        const int d   = tid & 127;
        const int cg  = tid >> 7;
        const int c0  = (cg < 2) ? 3 * cg : 6 + 2 * (cg - 2);
        const int cnt = (cg < 2) ? 3 : 2;
        float e[3] = {0.f, 0.f, 0.f};
        for (int m = 0; m < NPG; ++m) {
            float h = Hs[m * HS_LD + d];
#pragma unroll
            for (int j = 0; j < 3; ++j)
                if (j < cnt) e[j] = fmaf(Ss[m * NC + c0 + j], h, e[j]);
        }
        float* Eout = out + E_OFF + (size_t)g * (NC * D);
#pragma unroll
        for (int j = 0; j < 3; ++j)
            if (j < cnt) {
                Eout[(c0 + j) * D + d] = e[j];
                Es[(c0 + j) * D + d]   = e[j];
            }
#pragma unroll
        for (int r = 0; r < 2; ++r) p1s[tid + 512 * r] = pf[r];
        if (tid < 128) p2s[tid] = pf2;
    }
    __syncthreads();

    // ======================= fused downstream ================================
    float* ts    = sm + TS_OFF;
    float* qraw  = sm + QR_OFF;
    float* fms   = sm + FM_OFF;
    float* red   = sm + RED_OFF;
    float* sc    = sm + SC_OFF;
    float* corrs = sm + CORR_OFF;
    float* cmask = sm + CM_OFF;

    // ---- pred1 (wf streamed from L2) ---------------------------------------
    float s0 = 0.f, s1 = 0.f;
#pragma unroll
    for (int r = 0; r < 3; ++r) {
        int i = tid + 512 * r;
        if (i < 1280) {
            float e = Es[i];
            float2 w = __ldg((const float2*)(wf + 2 * i));
            s0 = fmaf(e, w.x, s0);
            s1 = fmaf(e, w.y, s1);
        }
    }
#pragma unroll
    for (int off = 16; off; off >>= 1) {
        s0 += __shfl_down_sync(0xffffffffu, s0, off);
        s1 += __shfl_down_sync(0xffffffffu, s1, off);
    }
    if (lane == 0) { red[wid * 2] = s0; red[wid * 2 + 1] = s1; }
    __syncthreads();

    if (tid == 0) {
        float z0 = bf[0], z1 = bf[1];
#pragma unroll
        for (int w = 0; w < 16; ++w) { z0 += red[2 * w]; z1 += red[2 * w + 1]; }
        out[P1_OFF + g * 2 + 0] = z0;
        out[P1_OFF + g * 2 + 1] = z1;
        float mx = fmaxf(z0, z1);
        float e0 = expf(z0 - mx), e1 = expf(z1 - mx);
        float inv = 1.0f / (e0 + e1);
        float pp0 = e0 * inv, pp1 = e1 * inv;

        float u0 = jax_unit_uniform(2u * g);
        float u1 = jax_unit_uniform(2u * g + 1u);
        float l0 = logf(pp0 + 1e-12f) - logf(-logf(u0));
        float l1 = logf(pp1 + 1e-12f) - logf(-logf(u1));
        int sample = (l1 > l0) ? 1 : 0;

        out[IND_OFF + g] = (sample == targets[g]) ? 1.0f : 0.0f;
        sc[0] = pp0 + ((sample == 0) ? (1.0f - pp0) : -pp0);
        sc[1] = pp1 + ((sample == 1) ? (1.0f - pp1) : -pp1);
    }

    // correlation = softmax(ci, axis=0) * softmax(cia, axis=1)   [2,16]
    if (tid >= 32 && tid < 64) {
        int t = tid - 32;
        int c = t >> 4, f = t & 15;
        float a0 = __ldg(&ci[f]), a1 = __ldg(&ci[16 + f]);
        float m = fmaxf(a0, a1);
        float e0 = expf(a0 - m), e1 = expf(a1 - m);
        float colv = ((c == 0) ? e0 : e1) / (e0 + e1);
        float rm = -1e30f;
        for (int ff = 0; ff < 16; ++ff) rm = fmaxf(rm, __ldg(&cia[c * 16 + ff]));
        float rs = 0.f;
        for (int ff = 0; ff < 16; ++ff) rs += expf(__ldg(&cia[c * 16 + ff]) - rm);
        corrs[c * 16 + f] = colv * (expf(__ldg(&cia[c * 16 + f]) - rm) / rs);
    }

    // ---- Q hidden layer: t = relu(E @ p1 + pb1)  [10][8] --------------------
    if (tid >= 64 && tid < 144) {
        int t = tid - 64;
        int c = t >> 3, j = t & 7;
        float a = __ldg(&pb1[j]);
        for (int k = 0; k < 128; ++k)
            a = fmaf(Es[c * 128 + k], p1s[k * 8 + j], a);
        ts[t] = fmaxf(a, 0.0f);
    }
    __syncthreads();

    if (tid < 16) cmask[tid] = sc[0] * corrs[tid] + sc[1] * corrs[16 + tid];

    // ---- Q output layer  [10][16] -------------------------------------------
    if (tid < 160) {
        int c = tid >> 4, f = tid & 15;
        float a = __ldg(&pb2[f]);
#pragma unroll
        for (int j = 0; j < 8; ++j) a = fmaf(ts[c * 8 + j], p2s[j * 16 + f], a);
        qraw[tid] = a;
    }
    __syncthreads();

    if (tid < NC) {
        int c = tid;
        float mx = -1e30f;
        for (int f = 0; f < 16; ++f) mx = fmaxf(mx, qraw[c * 16 + f]);
        float ssum = 0.f;
        for (int f = 0; f < 16; ++f) ssum += expf(qraw[c * 16 + f] - mx);
        float inv = 1.0f / ssum;
        float fm = 0.f;
        float* qout = out + Q_OFF + (size_t)g * 160 + c * 16;
        for (int f = 0; f < 16; ++f) {
            float q = expf(qraw[c * 16 + f] - mx) * inv;
            qout[f] = q;
            fm = fmaf(q, cmask[f], fm);
        }
        fms[c] = fm;
    }
    __syncthreads();

    // ---- pred2 --------------------------------------------------------------
    s0 = 0.f; s1 = 0.f;
#pragma unroll
    for (int r = 0; r < 3; ++r) {
        int i = tid + 512 * r;
        if (i < 1280) {
            float e = fms[i >> 7] * Es[i];
            float2 w = __ldg((const float2*)(wf + 2 * i));
            s0 = fmaf(e, w.x, s0);
            s1 = fmaf(e, w.y, s1);
        }
    }
#pragma unroll
    for (int off = 16; off; off >>= 1) {
        s0 += __shfl_down_sync(0xffffffffu, s0, off);
        s1 += __shfl_down_sync(0xffffffffu, s1, off);
    }
    if (lane == 0) { red[wid * 2] = s0; red[wid * 2 + 1] = s1; }
    __syncthreads();
    if (tid == 0) {
        float z0 = bf[0], z1 = bf[1];
#pragma unroll
        for (int w = 0; w < 16; ++w) { z0 += red[2 * w]; z1 += red[2 * w + 1]; }
        out[P2_OFF + g * 2 + 0] = z0;
        out[P2_OFF + g * 2 + 1] = z1;
    }
}

// ---------------------------------------------------------------------------
extern "C" void kernel_launch(void* const* d_in, const int* in_sizes, int n_in,
                              void* d_out, int out_size)
{
    const float* H   = (const float*)d_in[0];
    const int*   tgt = (const int*)  d_in[2];
    const float* w1  = (const float*)d_in[3];
    const float* b1  = (const float*)d_in[4];
    const float* w2  = (const float*)d_in[5];
    const float* b2  = (const float*)d_in[6];
    const float* wf  = (const float*)d_in[7];
    const float* bf  = (const float*)d_in[8];
    const float* p1  = (const float*)d_in[9];
    const float* pb1 = (const float*)d_in[10];
    const float* p2  = (const float*)d_in[11];
    const float* pb2 = (const float*)d_in[12];
    const float* ci  = (const float*)d_in[13];
    const float* cia = (const float*)d_in[14];
    float* out = (float*)d_out;

    const int smem = SM_FLOATS * 4;
    static bool attr_set = false;
    if (!attr_set) {
        cudaFuncSetAttribute(ciflow_fused,
                             cudaFuncAttributeMaxDynamicSharedMemorySize, smem);
        attr_set = true;
    }

    ciflow_fused<<<NGRAPH, 512, smem>>>(H, tgt, w1, b1, w2, b2, wf, bf,
                                        p1, pb1, p2, pb2, ci, cia, out);
}

// round 4
// speedup vs baseline: 1.3736x; 1.2237x over previous
#include <cuda_runtime.h>
#include <cstdint>

// Problem constants
#define NGRAPH 512
#define NPG    125
#define D      128
#define SH     69           // S_HID
#define SHP    80           // padded S_HID
#define NC     10           // clusters
#define HS_LD  130          // H row stride (even: float2-aligned, conflict-free)
#define HS_LD2 65
#define W1T_LD 130          // W1^T row stride
#define W1T_LD2 65
#define AS_LD  81           // A row stride (odd: conflict-free in stage Z)

// d_out float offsets (outputs concatenated in return order)
#define P1_OFF  0
#define P2_OFF  1024
#define IND_OFF 2048
#define S_OFF   2560
#define E_OFF   642560
#define Q_OFF   1297920

// Shared-memory layout (float offsets) — total 113.5 KB -> 2 CTAs/SM
#define HS_OFF   0           // H [128][130] = 16640 f ; later aliased by As[125][81]
#define W1T_OFF  16640       // W1^T [80][130] = 10400 f ; later aliased by tail temps
#define SS_OFF   27040       // S [125][10] = 1250
#define B1_OFF   28290       // [80]
#define SM_FLOATS 28372      // 113,488 bytes

// tail temporaries aliased into the W1T region (dead after stage A)
#define ES_OFF   16640       // 1280
#define P1S_OFF  17920       // 1024
#define P2S_OFF  18944       // 128
#define TS_OFF   19072       // 80
#define QR_OFF   19152       // 160
#define FM_OFF   19312       // 16
#define RED_OFF  19328       // 32
#define SC_OFF   19360       // 2
#define CORR_OFF 19368       // 32
#define CM_OFF   19400       // 16
#define W2S_OFF  19424       // 690 (live only during stage Z)

// ---------------------------------------------------------------------------
// Threefry-2x32 (JAX partitionable path) — verified bit-exact R1-R3
// ---------------------------------------------------------------------------
__device__ __forceinline__ void threefry2x32(uint32_t k0, uint32_t k1,
                                             uint32_t c0, uint32_t c1,
                                             uint32_t& y0, uint32_t& y1)
{
    uint32_t ks2 = k0 ^ k1 ^ 0x1BD11BDAu;
    uint32_t x0 = c0 + k0, x1 = c1 + k1;
#define TF_RND(r) { x0 += x1; x1 = (x1 << (r)) | (x1 >> (32 - (r))); x1 ^= x0; }
    TF_RND(13) TF_RND(15) TF_RND(26) TF_RND(6)  x0 += k1;  x1 += ks2 + 1u;
    TF_RND(17) TF_RND(29) TF_RND(16) TF_RND(24) x0 += ks2; x1 += k0  + 2u;
    TF_RND(13) TF_RND(15) TF_RND(26) TF_RND(6)  x0 += k0;  x1 += k1  + 3u;
    TF_RND(17) TF_RND(29) TF_RND(16) TF_RND(24) x0 += k1;  x1 += ks2 + 4u;
    TF_RND(13) TF_RND(15) TF_RND(26) TF_RND(6)  x0 += ks2; x1 += k0  + 5u;
#undef TF_RND
    y0 = x0; y1 = x1;
}
__device__ __forceinline__ float jax_unit_uniform(uint32_t f)
{
    uint32_t y0, y1;
    threefry2x32(0u, 42u, 0u, f, y0, y1);
    uint32_t bits = y0 ^ y1;
    float v = __uint_as_float((bits >> 9) | 0x3f800000u) - 1.0f;
    return (v == 0.0f) ? 1.17549435e-38f : v;
}

// ---------------------------------------------------------------------------
// Fully fused kernel: one block per graph, 512 threads, 2 CTAs/SM.
// ---------------------------------------------------------------------------
__global__ __launch_bounds__(512, 2) void ciflow_fused(
    const float* __restrict__ H,
    const int*   __restrict__ targets,
    const float* __restrict__ w1,  const float* __restrict__ b1,
    const float* __restrict__ w2,  const float* __restrict__ b2,
    const float* __restrict__ wf,  const float* __restrict__ bf,
    const float* __restrict__ p1,  const float* __restrict__ pb1,
    const float* __restrict__ p2,  const float* __restrict__ pb2,
    const float* __restrict__ ci,  const float* __restrict__ cia,
    float* __restrict__ out)
{
    extern __shared__ float sm[];
    float* Hs  = sm + HS_OFF;
    float* W1t = sm + W1T_OFF;
    float* As  = sm + HS_OFF;    // aliases Hs after stage A (E reads H from L2)
    float* Ss  = sm + SS_OFF;
    float* b1s = sm + B1_OFF;

    const int g    = blockIdx.x;
    const int tid  = threadIdx.x;
    const int lane = tid & 31;
    const int wid  = tid >> 5;

    // ---- cooperative loads --------------------------------------------------
    const float* Hg = H + (size_t)g * NPG * D;
    for (int idx = tid; idx < NPG * D; idx += 512) {
        int m = idx >> 7, k = idx & 127;
        Hs[m * HS_LD + k] = Hg[idx];
    }
    for (int idx = tid; idx < 3 * HS_LD; idx += 512)
        Hs[NPG * HS_LD + idx] = 0.0f;                        // zero rows 125..127
    for (int idx = tid; idx < 128 * SHP; idx += 512) {       // W1 transposed
        int k = idx / SHP, n = idx - k * SHP;                // consecutive n -> coalesced
        W1t[n * W1T_LD + k] = (n < SH) ? w1[k * SH + n] : 0.0f;
    }
    if (tid < SHP) b1s[tid] = (tid < SH) ? b1[tid] : 0.0f;
    __syncthreads();

    // ---- stage A: A = relu(H @ w1 + b1), float2 along k ---------------------
    // 32 tx (M) x 16 ty (N): 4 rows (tx+32i) x 5 cols (ty+16j) per thread.
    const int tx = tid & 31;
    const int ty = tid >> 5;
    float acc[4][5];
#pragma unroll
    for (int i = 0; i < 4; ++i)
#pragma unroll
        for (int j = 0; j < 5; ++j) acc[i][j] = 0.0f;

    const float2* Hs2  = (const float2*)(sm + HS_OFF);
    const float2* W1t2 = (const float2*)(sm + W1T_OFF);
#pragma unroll 2
    for (int kk = 0; kk < 64; ++kk) {
        float2 h2[4], wv[5];
#pragma unroll
        for (int i = 0; i < 4; ++i) h2[i] = Hs2[(tx + 32 * i) * HS_LD2 + kk];
#pragma unroll
        for (int j = 0; j < 5; ++j) wv[j] = W1t2[(ty + 16 * j) * W1T_LD2 + kk];
#pragma unroll
        for (int i = 0; i < 4; ++i)
#pragma unroll
            for (int j = 0; j < 5; ++j) {
                acc[i][j] = fmaf(h2[i].x, wv[j].x, acc[i][j]);
                acc[i][j] = fmaf(h2[i].y, wv[j].y, acc[i][j]);
            }
    }
    __syncthreads();            // Hs/W1t reads done before aliasing

    // epilogue: As -> Hs region; stage W2 into freed W1t region
    float* W2s = sm + W2S_OFF;
#pragma unroll
    for (int i = 0; i < 4; ++i) {
        int m = tx + 32 * i;
#pragma unroll
        for (int j = 0; j < 5; ++j) {
            int n = ty + 16 * j;
            As[m * AS_LD + n] = fmaxf(acc[i][j] + b1s[n], 0.0f);
        }
    }
    for (int idx = tid; idx < SH * NC; idx += 512) W2s[idx] = w2[idx];
    __syncthreads();

    // ---- stage Z: z = A @ w2 + b2, softmax -> S (2 threads per row) ---------
    if (tid < 256) {
        const int m    = tid >> 1;
        const int half = tid & 1;
        const int cb   = 5 * half;
        float z[5];
#pragma unroll
        for (int c = 0; c < 5; ++c) z[c] = __ldg(&b2[cb + c]);
        for (int n = 0; n < SH; ++n) {
            float a = As[m * AS_LD + n];
#pragma unroll
            for (int c = 0; c < 5; ++c) z[c] = fmaf(a, W2s[n * NC + cb + c], z[c]);
        }
        float mx = z[0];
#pragma unroll
        for (int c = 1; c < 5; ++c) mx = fmaxf(mx, z[c]);
        mx = fmaxf(mx, __shfl_xor_sync(0xffffffffu, mx, 1));
        float ssum = 0.0f;
#pragma unroll
        for (int c = 0; c < 5; ++c) { z[c] = expf(z[c] - mx); ssum += z[c]; }
        ssum += __shfl_xor_sync(0xffffffffu, ssum, 1);
        float inv = 1.0f / ssum;
        if (m < NPG) {
            float* srow = &Ss[m * NC + cb];
            float* gout = out + S_OFF + ((size_t)g * NPG + m) * NC + cb;
#pragma unroll
            for (int c = 0; c < 5; ++c) {
                float s = z[c] * inv;
                srow[c] = s;
                gout[c] = s;
            }
        }
    }
    __syncthreads();

    // ---- stage E: E[c][d] = sum_m S[m][c] H[m][d]; H from L2 ---------------
    // c-groups per (tid>>7): starts {0,3,6,8}, counts {3,3,2,2}
    float* Es  = sm + ES_OFF;
    float* p1s = sm + P1S_OFF;
    float* p2s = sm + P2S_OFF;
    {
        float pf[2];
#pragma unroll
        for (int r = 0; r < 2; ++r) pf[r] = __ldg(&p1[tid + 512 * r]);
        float pf2 = (tid < 128) ? __ldg(&p2[tid]) : 0.0f;

        const int d   = tid & 127;
        const int cg  = tid >> 7;
        const int c0  = (cg < 2) ? 3 * cg : 6 + 2 * (cg - 2);
        const int cnt = (cg < 2) ? 3 : 2;
        float e[3] = {0.f, 0.f, 0.f};
#pragma unroll 5
        for (int m = 0; m < NPG; ++m) {
            float h = __ldg(&Hg[m * D + d]);
#pragma unroll
            for (int j = 0; j < 3; ++j)
                if (j < cnt) e[j] = fmaf(Ss[m * NC + c0 + j], h, e[j]);
        }
        float* Eout = out + E_OFF + (size_t)g * (NC * D);
#pragma unroll
        for (int j = 0; j < 3; ++j)
            if (j < cnt) {
                Eout[(c0 + j) * D + d] = e[j];
                Es[(c0 + j) * D + d]   = e[j];
            }
#pragma unroll
        for (int r = 0; r < 2; ++r) p1s[tid + 512 * r] = pf[r];
        if (tid < 128) p2s[tid] = pf2;
    }
    __syncthreads();

    // ======================= fused downstream ================================
    float* ts    = sm + TS_OFF;
    float* qraw  = sm + QR_OFF;
    float* fms   = sm + FM_OFF;
    float* red   = sm + RED_OFF;
    float* sc    = sm + SC_OFF;
    float* corrs = sm + CORR_OFF;
    float* cmask = sm + CM_OFF;

    // ---- pred1 (wf streamed from L2) ---------------------------------------
    float s0 = 0.f, s1 = 0.f;
#pragma unroll
    for (int r = 0; r < 3; ++r) {
        int i = tid + 512 * r;
        if (i < 1280) {
            float e = Es[i];
            float2 w = __ldg((const float2*)(wf + 2 * i));
            s0 = fmaf(e, w.x, s0);
            s1 = fmaf(e, w.y, s1);
        }
    }
#pragma unroll
    for (int off = 16; off; off >>= 1) {
        s0 += __shfl_down_sync(0xffffffffu, s0, off);
        s1 += __shfl_down_sync(0xffffffffu, s1, off);
    }
    if (lane == 0) { red[wid * 2] = s0; red[wid * 2 + 1] = s1; }
    __syncthreads();

    if (tid == 0) {
        float z0 = bf[0], z1 = bf[1];
#pragma unroll
        for (int w = 0; w < 16; ++w) { z0 += red[2 * w]; z1 += red[2 * w + 1]; }
        out[P1_OFF + g * 2 + 0] = z0;
        out[P1_OFF + g * 2 + 1] = z1;
        float mx = fmaxf(z0, z1);
        float e0 = expf(z0 - mx), e1 = expf(z1 - mx);
        float inv = 1.0f / (e0 + e1);
        float pp0 = e0 * inv, pp1 = e1 * inv;

        float u0 = jax_unit_uniform(2u * g);
        float u1 = jax_unit_uniform(2u * g + 1u);
        float l0 = logf(pp0 + 1e-12f) - logf(-logf(u0));
        float l1 = logf(pp1 + 1e-12f) - logf(-logf(u1));
        int sample = (l1 > l0) ? 1 : 0;

        out[IND_OFF + g] = (sample == targets[g]) ? 1.0f : 0.0f;
        sc[0] = pp0 + ((sample == 0) ? (1.0f - pp0) : -pp0);
        sc[1] = pp1 + ((sample == 1) ? (1.0f - pp1) : -pp1);
    }

    // correlation = softmax(ci, axis=0) * softmax(cia, axis=1)   [2,16]
    if (tid >= 32 && tid < 64) {
        int t = tid - 32;
        int c = t >> 4, f = t & 15;
        float a0 = __ldg(&ci[f]), a1 = __ldg(&ci[16 + f]);
        float m = fmaxf(a0, a1);
        float e0 = expf(a0 - m), e1 = expf(a1 - m);
        float colv = ((c == 0) ? e0 : e1) / (e0 + e1);
        float rm = -1e30f;
        for (int ff = 0; ff < 16; ++ff) rm = fmaxf(rm, __ldg(&cia[c * 16 + ff]));
        float rs = 0.f;
        for (int ff = 0; ff < 16; ++ff) rs += expf(__ldg(&cia[c * 16 + ff]) - rm);
        corrs[c * 16 + f] = colv * (expf(__ldg(&cia[c * 16 + f]) - rm) / rs);
    }

    // ---- Q hidden layer: t = relu(E @ p1 + pb1)  [10][8] --------------------
    if (tid >= 64 && tid < 144) {
        int t = tid - 64;
        int c = t >> 3, j = t & 7;
        float a = __ldg(&pb1[j]);
        for (int k = 0; k < 128; ++k)
            a = fmaf(Es[c * 128 + k], p1s[k * 8 + j], a);
        ts[t] = fmaxf(a, 0.0f);
    }
    __syncthreads();

    if (tid < 16) cmask[tid] = sc[0] * corrs[tid] + sc[1] * corrs[16 + tid];

    // ---- Q output layer  [10][16] -------------------------------------------
    if (tid < 160) {
        int c = tid >> 4, f = tid & 15;
        float a = __ldg(&pb2[f]);
#pragma unroll
        for (int j = 0; j < 8; ++j) a = fmaf(ts[c * 8 + j], p2s[j * 16 + f], a);
        qraw[tid] = a;
    }
    __syncthreads();

    if (tid < NC) {
        int c = tid;
        float mx = -1e30f;
        for (int f = 0; f < 16; ++f) mx = fmaxf(mx, qraw[c * 16 + f]);
        float ssum = 0.f;
        for (int f = 0; f < 16; ++f) ssum += expf(qraw[c * 16 + f] - mx);
        float inv = 1.0f / ssum;
        float fm = 0.f;
        float* qout = out + Q_OFF + (size_t)g * 160 + c * 16;
        for (int f = 0; f < 16; ++f) {
            float q = expf(qraw[c * 16 + f] - mx) * inv;
            qout[f] = q;
            fm = fmaf(q, cmask[f], fm);
        }
        fms[c] = fm;
    }
    __syncthreads();

    // ---- pred2 --------------------------------------------------------------
    s0 = 0.f; s1 = 0.f;
#pragma unroll
    for (int r = 0; r < 3; ++r) {
        int i = tid + 512 * r;
        if (i < 1280) {
            float e = fms[i >> 7] * Es[i];
            float2 w = __ldg((const float2*)(wf + 2 * i));
            s0 = fmaf(e, w.x, s0);
            s1 = fmaf(e, w.y, s1);
        }
    }
#pragma unroll
    for (int off = 16; off; off >>= 1) {
        s0 += __shfl_down_sync(0xffffffffu, s0, off);
        s1 += __shfl_down_sync(0xffffffffu, s1, off);
    }
    if (lane == 0) { red[wid * 2] = s0; red[wid * 2 + 1] = s1; }
    __syncthreads();
    if (tid == 0) {
        float z0 = bf[0], z1 = bf[1];
#pragma unroll
        for (int w = 0; w < 16; ++w) { z0 += red[2 * w]; z1 += red[2 * w + 1]; }
        out[P2_OFF + g * 2 + 0] = z0;
        out[P2_OFF + g * 2 + 1] = z1;
    }
}

// ---------------------------------------------------------------------------
extern "C" void kernel_launch(void* const* d_in, const int* in_sizes, int n_in,
                              void* d_out, int out_size)
{
    const float* H   = (const float*)d_in[0];
    const int*   tgt = (const int*)  d_in[2];
    const float* w1  = (const float*)d_in[3];
    const float* b1  = (const float*)d_in[4];
    const float* w2  = (const float*)d_in[5];
    const float* b2  = (const float*)d_in[6];
    const float* wf  = (const float*)d_in[7];
    const float* bf  = (const float*)d_in[8];
    const float* p1  = (const float*)d_in[9];
    const float* pb1 = (const float*)d_in[10];
    const float* p2  = (const float*)d_in[11];
    const float* pb2 = (const float*)d_in[12];
    const float* ci  = (const float*)d_in[13];
    const float* cia = (const float*)d_in[14];
    float* out = (float*)d_out;

    const int smem = SM_FLOATS * 4;
    static bool attr_set = false;
    if (!attr_set) {
        cudaFuncSetAttribute(ciflow_fused,
                             cudaFuncAttributeMaxDynamicSharedMemorySize, smem);
        attr_set = true;
    }

    ciflow_fused<<<NGRAPH, 512, smem>>>(H, tgt, w1, b1, w2, b2, wf, bf,
                                        p1, pb1, p2, pb2, ci, cia, out);
}

// round 6
// speedup vs baseline: 1.4401x; 1.0485x over previous
#include <cuda_runtime.h>
#include <cstdint>

// Problem constants
#define NGRAPH 512
#define NPG    125
#define D      128
#define SH     69           // S_HID
#define NC     10
#define HS_LD  130          // H row stride (float2-aligned, conflict-free)
#define HS_LD2 65
#define W1T_LD 130
#define W1T_LD2 65
#define AS_LD  73           // odd -> conflict-free row reads in stage Z

// d_out float offsets (outputs concatenated in return order)
#define P1_OFF  0
#define P2_OFF  1024
#define IND_OFF 2048
#define S_OFF   2560
#define E_OFF   642560
#define Q_OFF   1297920

// ---- smem layout (float offsets), total 28104 f = 112,416 B -> 2 CTAs/SM --
#define HS_F    0            // H [128][130] = 16640 (live through stage E)
#define W1T_F   16640        // W1^T [72][130] = 9360 (dead after stage A)
#define AS_F    16640        //   alias: As [128][73] = 9344
#define ES_F    16640        //   alias after stage Z: Es 1280
#define P1S_F   17920        //   p1s 1024
#define P2S_F   18944        //   p2s 128
#define TS_F    19072        //   ts 80
#define QR_F    19152        //   qraw 160
#define FM_F    19312        //   fms 16
// persistent
#define SS_F    26000        // S [125][10] = 1250
#define B1S_F   27250        // 80
#define W2S_F   27330        // 690
#define RED_F   28020        // 32
#define SC_F    28052        // 2
#define CORR_F  28056        // 32
#define CM_F    28088        // 16
#define SM_FLOATS 28104

// ---------------------------------------------------------------------------
// Threefry-2x32 (JAX partitionable) — bit-exact since R1
// ---------------------------------------------------------------------------
__device__ __forceinline__ void threefry2x32(uint32_t k0, uint32_t k1,
                                             uint32_t c0, uint32_t c1,
                                             uint32_t& y0, uint32_t& y1)
{
    uint32_t ks2 = k0 ^ k1 ^ 0x1BD11BDAu;
    uint32_t x0 = c0 + k0, x1 = c1 + k1;
#define TF_RND(r) { x0 += x1; x1 = (x1 << (r)) | (x1 >> (32 - (r))); x1 ^= x0; }
    TF_RND(13) TF_RND(15) TF_RND(26) TF_RND(6)  x0 += k1;  x1 += ks2 + 1u;
    TF_RND(17) TF_RND(29) TF_RND(16) TF_RND(24) x0 += ks2; x1 += k0  + 2u;
    TF_RND(13) TF_RND(15) TF_RND(26) TF_RND(6)  x0 += k0;  x1 += k1  + 3u;
    TF_RND(17) TF_RND(29) TF_RND(16) TF_RND(24) x0 += k1;  x1 += ks2 + 4u;
    TF_RND(13) TF_RND(15) TF_RND(26) TF_RND(6)  x0 += ks2; x1 += k0  + 5u;
#undef TF_RND
    y0 = x0; y1 = x1;
}
__device__ __forceinline__ float jax_unit_uniform(uint32_t f)
{
    uint32_t y0, y1;
    threefry2x32(0u, 42u, 0u, f, y0, y1);
    uint32_t bits = y0 ^ y1;
    float v = __uint_as_float((bits >> 9) | 0x3f800000u) - 1.0f;
    return (v == 0.0f) ? 1.17549435e-38f : v;
}

// ---------------------------------------------------------------------------
// Stage A inner loop, NJ = columns per thread (warp-uniform 4 or 5).
// ---------------------------------------------------------------------------
template<int NJ>
__device__ __forceinline__ void stageA_loop(const float2* __restrict__ Hs2,
                                            const float2* __restrict__ W1t2,
                                            int tx, int ty, float acc[4][5])
{
#pragma unroll
    for (int i = 0; i < 4; ++i)
#pragma unroll
        for (int j = 0; j < NJ; ++j) acc[i][j] = 0.0f;

#pragma unroll 2
    for (int kk = 0; kk < 64; ++kk) {
        float2 h2[4], wv[NJ];
#pragma unroll
        for (int i = 0; i < 4; ++i) h2[i] = Hs2[(tx + 32 * i) * HS_LD2 + kk];
#pragma unroll
        for (int j = 0; j < NJ; ++j) wv[j] = W1t2[(ty + 16 * j) * W1T_LD2 + kk];
#pragma unroll
        for (int i = 0; i < 4; ++i)
#pragma unroll
            for (int j = 0; j < NJ; ++j) {
                acc[i][j] = fmaf(h2[i].x, wv[j].x, acc[i][j]);
                acc[i][j] = fmaf(h2[i].y, wv[j].y, acc[i][j]);
            }
    }
}

// ---------------------------------------------------------------------------
// Fused kernel: one block per graph, 512 threads, 2 CTAs/SM.
// ---------------------------------------------------------------------------
__global__ __launch_bounds__(512, 2) void ciflow_fused(
    const float* __restrict__ H,
    const int*   __restrict__ targets,
    const float* __restrict__ w1,  const float* __restrict__ b1,
    const float* __restrict__ w2,  const float* __restrict__ b2,
    const float* __restrict__ wf,  const float* __restrict__ bf,
    const float* __restrict__ p1,  const float* __restrict__ pb1,
    const float* __restrict__ p2,  const float* __restrict__ pb2,
    const float* __restrict__ ci,  const float* __restrict__ cia,
    float* __restrict__ out)
{
    extern __shared__ float sm[];
    float* Hs  = sm + HS_F;
    float* W1t = sm + W1T_F;
    float* As  = sm + AS_F;      // aliases W1t after stage A
    float* Ss  = sm + SS_F;
    float* b1s = sm + B1S_F;
    float* W2s = sm + W2S_F;

    const int g    = blockIdx.x;
    const int tid  = threadIdx.x;
    const int lane = tid & 31;
    const int wid  = tid >> 5;

    // ---- cooperative loads --------------------------------------------------
    const float* Hg = H + (size_t)g * NPG * D;
    for (int idx = tid; idx < NPG * D; idx += 512) {
        int m = idx >> 7, k = idx & 127;
        Hs[m * HS_LD + k] = Hg[idx];
    }
    for (int idx = tid; idx < 3 * HS_LD; idx += 512)
        Hs[NPG * HS_LD + idx] = 0.0f;                        // zero rows 125..127
    for (int idx = tid; idx < 72 * D; idx += 512) {          // W1 transposed
        int n = idx >> 7, k = idx & 127;
        W1t[n * W1T_LD + k] = (n < SH) ? w1[k * SH + n] : 0.0f;
    }
    for (int idx = tid; idx < SH * NC; idx += 512) W2s[idx] = w2[idx];
    if (tid < 72) b1s[tid] = (tid < SH) ? b1[tid] : 0.0f;
    __syncthreads();

    // ---- stage A: A = relu(H @ w1 + b1), cols 0..68 only --------------------
    // 32 tx (M) x 16 ty: 4 rows x {5 cols if ty<5 else 4 cols} per thread.
    const int tx = tid & 31;
    const int ty = tid >> 5;
    const int jmax = (ty < 5) ? 5 : 4;
    float acc[4][5];
    const float2* Hs2  = (const float2*)(sm + HS_F);
    const float2* W1t2 = (const float2*)(sm + W1T_F);
    if (ty < 5) stageA_loop<5>(Hs2, W1t2, tx, ty, acc);
    else        stageA_loop<4>(Hs2, W1t2, tx, ty, acc);
    __syncthreads();            // all W1t reads done before aliasing to As

#pragma unroll
    for (int i = 0; i < 4; ++i) {
        int m = tx + 32 * i;
#pragma unroll
        for (int j = 0; j < 5; ++j)
            if (j < jmax) {
                int n = ty + 16 * j;
                As[m * AS_LD + n] = fmaxf(acc[i][j] + b1s[n], 0.0f);
            }
    }
    __syncthreads();

    // ---- stage Z: z = A @ w2 + b2, softmax -> S (2 threads per row) ---------
    if (tid < 256) {
        const int m    = tid >> 1;
        const int half = tid & 1;
        const int cb   = 5 * half;
        float z[5];
#pragma unroll
        for (int c = 0; c < 5; ++c) z[c] = __ldg(&b2[cb + c]);
        for (int n = 0; n < SH; ++n) {
            float a = As[m * AS_LD + n];
#pragma unroll
            for (int c = 0; c < 5; ++c) z[c] = fmaf(a, W2s[n * NC + cb + c], z[c]);
        }
        float mx = z[0];
#pragma unroll
        for (int c = 1; c < 5; ++c) mx = fmaxf(mx, z[c]);
        mx = fmaxf(mx, __shfl_xor_sync(0xffffffffu, mx, 1));
        float ssum = 0.0f;
#pragma unroll
        for (int c = 0; c < 5; ++c) { z[c] = expf(z[c] - mx); ssum += z[c]; }
        ssum += __shfl_xor_sync(0xffffffffu, ssum, 1);
        float inv = 1.0f / ssum;
        if (m < NPG) {
            float* srow = &Ss[m * NC + cb];
            float* gout = out + S_OFF + ((size_t)g * NPG + m) * NC + cb;
#pragma unroll
            for (int c = 0; c < 5; ++c) {
                float s = z[c] * inv;
                srow[c] = s;
                gout[c] = s;
            }
        }
    }
    __syncthreads();

    // ---- stage E: E[c][d] = sum_m S[m][c] H[m][d]; H from smem --------------
    // c-groups per (tid>>7): starts {0,3,6,8}, counts {3,3,2,2}
    float* Es  = sm + ES_F;
    float* p1s = sm + P1S_F;
    float* p2s = sm + P2S_F;
    {
        float pf[2];
#pragma unroll
        for (int r = 0; r < 2; ++r) pf[r] = __ldg(&p1[tid + 512 * r]);
        float pf2 = (tid < 128) ? __ldg(&p2[tid]) : 0.0f;

        const int d   = tid & 127;
        const int cg  = tid >> 7;
        const int c0  = (cg < 2) ? 3 * cg : 6 + 2 * (cg - 2);
        const int cnt = (cg < 2) ? 3 : 2;
        float e[3] = {0.f, 0.f, 0.f};
#pragma unroll 5
        for (int m = 0; m < NPG; ++m) {
            float h = Hs[m * HS_LD + d];
#pragma unroll
            for (int j = 0; j < 3; ++j)
                if (j < cnt) e[j] = fmaf(Ss[m * NC + c0 + j], h, e[j]);
        }
        float* Eout = out + E_OFF + (size_t)g * (NC * D);
#pragma unroll
        for (int j = 0; j < 3; ++j)
            if (j < cnt) {
                Eout[(c0 + j) * D + d] = e[j];
                Es[(c0 + j) * D + d]   = e[j];
            }
#pragma unroll
        for (int r = 0; r < 2; ++r) p1s[tid + 512 * r] = pf[r];
        if (tid < 128) p2s[tid] = pf2;
    }
    __syncthreads();

    // ======================= fused downstream ================================
    float* ts    = sm + TS_F;
    float* qraw  = sm + QR_F;
    float* fms   = sm + FM_F;
    float* red   = sm + RED_F;
    float* sc    = sm + SC_F;
    float* corrs = sm + CORR_F;
    float* cmask = sm + CM_F;

    // ---- pred1 ---------------------------------------------------------------
    float s0 = 0.f, s1 = 0.f;
#pragma unroll
    for (int r = 0; r < 3; ++r) {
        int i = tid + 512 * r;
        if (i < 1280) {
            float e = Es[i];
            float2 w = __ldg((const float2*)(wf + 2 * i));
            s0 = fmaf(e, w.x, s0);
            s1 = fmaf(e, w.y, s1);
        }
    }
#pragma unroll
    for (int off = 16; off; off >>= 1) {
        s0 += __shfl_down_sync(0xffffffffu, s0, off);
        s1 += __shfl_down_sync(0xffffffffu, s1, off);
    }
    if (lane == 0) { red[wid * 2] = s0; red[wid * 2 + 1] = s1; }
    __syncthreads();

    if (tid == 0) {
        float z0 = bf[0], z1 = bf[1];
#pragma unroll
        for (int w = 0; w < 16; ++w) { z0 += red[2 * w]; z1 += red[2 * w + 1]; }
        out[P1_OFF + g * 2 + 0] = z0;
        out[P1_OFF + g * 2 + 1] = z1;
        float mx = fmaxf(z0, z1);
        float e0 = expf(z0 - mx), e1 = expf(z1 - mx);
        float inv = 1.0f / (e0 + e1);
        float pp0 = e0 * inv, pp1 = e1 * inv;

        float u0 = jax_unit_uniform(2u * g);
        float u1 = jax_unit_uniform(2u * g + 1u);
        float l0 = logf(pp0 + 1e-12f) - logf(-logf(u0));
        float l1 = logf(pp1 + 1e-12f) - logf(-logf(u1));
        int sample = (l1 > l0) ? 1 : 0;

        out[IND_OFF + g] = (sample == targets[g]) ? 1.0f : 0.0f;
        sc[0] = pp0 + ((sample == 0) ? (1.0f - pp0) : -pp0);
        sc[1] = pp1 + ((sample == 1) ? (1.0f - pp1) : -pp1);
    }

    // correlation = softmax(ci, axis=0) * softmax(cia, axis=1)   [2,16]
    if (tid >= 32 && tid < 64) {
        int t = tid - 32;
        int c = t >> 4, f = t & 15;
        float a0 = __ldg(&ci[f]), a1 = __ldg(&ci[16 + f]);
        float m = fmaxf(a0, a1);
        float e0 = expf(a0 - m), e1 = expf(a1 - m);
        float colv = ((c == 0) ? e0 : e1) / (e0 + e1);
        float rm = -1e30f;
        for (int ff = 0; ff < 16; ++ff) rm = fmaxf(rm, __ldg(&cia[c * 16 + ff]));
        float rs = 0.f;
        for (int ff = 0; ff < 16; ++ff) rs += expf(__ldg(&cia[c * 16 + ff]) - rm);
        corrs[c * 16 + f] = colv * (expf(__ldg(&cia[c * 16 + f]) - rm) / rs);
    }

    // ---- Q hidden layer: t = relu(E @ p1 + pb1)  [10][8] --------------------
    if (tid >= 64 && tid < 144) {
        int t = tid - 64;
        int c = t >> 3, j = t & 7;
        float a = __ldg(&pb1[j]);
        for (int k = 0; k < 128; ++k)
            a = fmaf(Es[c * 128 + k], p1s[k * 8 + j], a);
        ts[t] = fmaxf(a, 0.0f);
    }
    __syncthreads();

    if (tid < 16) cmask[tid] = sc[0] * corrs[tid] + sc[1] * corrs[16 + tid];

    // ---- Q output layer  [10][16] -------------------------------------------
    if (tid < 160) {
        int c = tid >> 4, f = tid & 15;
        float a = __ldg(&pb2[f]);
#pragma unroll
        for (int j = 0; j < 8; ++j) a = fmaf(ts[c * 8 + j], p2s[j * 16 + f], a);
        qraw[tid] = a;
    }
    __syncthreads();

    if (tid < NC) {
        int c = tid;
        float mx = -1e30f;
        for (int f = 0; f < 16; ++f) mx = fmaxf(mx, qraw[c * 16 + f]);
        float ssum = 0.f;
        for (int f = 0; f < 16; ++f) ssum += expf(qraw[c * 16 + f] - mx);
        float inv = 1.0f / ssum;
        float fm = 0.f;
        float* qout = out + Q_OFF + (size_t)g * 160 + c * 16;
        for (int f = 0; f < 16; ++f) {
            float q = expf(qraw[c * 16 + f] - mx) * inv;
            qout[f] = q;
            fm = fmaf(q, cmask[f], fm);
        }
        fms[c] = fm;
    }
    __syncthreads();

    // ---- pred2 ---------------------------------------------------------------
    s0 = 0.f; s1 = 0.f;
#pragma unroll
    for (int r = 0; r < 3; ++r) {
        int i = tid + 512 * r;
        if (i < 1280) {
            float e = fms[i >> 7] * Es[i];
            float2 w = __ldg((const float2*)(wf + 2 * i));
            s0 = fmaf(e, w.x, s0);
            s1 = fmaf(e, w.y, s1);
        }
    }
#pragma unroll
    for (int off = 16; off; off >>= 1) {
        s0 += __shfl_down_sync(0xffffffffu, s0, off);
        s1 += __shfl_down_sync(0xffffffffu, s1, off);
    }
    if (lane == 0) { red[wid * 2] = s0; red[wid * 2 + 1] = s1; }
    __syncthreads();
    if (tid == 0) {
        float z0 = bf[0], z1 = bf[1];
#pragma unroll
        for (int w = 0; w < 16; ++w) { z0 += red[2 * w]; z1 += red[2 * w + 1]; }
        out[P2_OFF + g * 2 + 0] = z0;
        out[P2_OFF + g * 2 + 1] = z1;
    }
}

// ---------------------------------------------------------------------------
extern "C" void kernel_launch(void* const* d_in, const int* in_sizes, int n_in,
                              void* d_out, int out_size)
{
    const float* H   = (const float*)d_in[0];
    const int*   tgt = (const int*)  d_in[2];
    const float* w1  = (const float*)d_in[3];
    const float* b1  = (const float*)d_in[4];
    const float* w2  = (const float*)d_in[5];
    const float* b2  = (const float*)d_in[6];
    const float* wf  = (const float*)d_in[7];
    const float* bf  = (const float*)d_in[8];
    const float* p1  = (const float*)d_in[9];
    const float* pb1 = (const float*)d_in[10];
    const float* p2  = (const float*)d_in[11];
    const float* pb2 = (const float*)d_in[12];
    const float* ci  = (const float*)d_in[13];
    const float* cia = (const float*)d_in[14];
    float* out = (float*)d_out;

    const int smem = SM_FLOATS * 4;
    static bool attr_set = false;
    if (!attr_set) {
        cudaFuncSetAttribute(ciflow_fused,
                             cudaFuncAttributeMaxDynamicSharedMemorySize, smem);
        attr_set = true;
    }

    ciflow_fused<<<NGRAPH, 512, smem>>>(H, tgt, w1, b1, w2, b2, wf, bf,
                                        p1, pb1, p2, pb2, ci, cia, out);
}

// round 7
// speedup vs baseline: 1.4454x; 1.0037x over previous
#include <cuda_runtime.h>
#include <cstdint>

// Problem constants
#define NGRAPH 512
#define NPG    125
#define D      128
#define SH     69           // S_HID
#define NC     10
#define HS_LD  132          // H row stride in floats (f4-aligned; f4 stride 33 odd)
#define HS_LD4 33
#define W1T_LD 132
#define W1T_LD4 33
#define AS_LD  73           // odd -> conflict-free row reads in stage Z

// d_out float offsets (outputs concatenated in return order)
#define P1_OFF  0
#define P2_OFF  1024
#define IND_OFF 2048
#define S_OFF   2560
#define E_OFF   642560
#define Q_OFF   1297920

// ---- smem layout (float offsets), total 28504 f = 114,016 B -> 2 CTAs/SM --
#define HS_F    0            // H [128][132] = 16896 (live through stage E)
#define W1T_F   16896        // W1^T [72][132] = 9504 (dead after stage A)
#define AS_F    16896        //   alias: As [128][73] = 9344
#define ES_F    16896        //   alias after stage Z: Es 1280
#define P1S_F   18176        //   p1s 1024
#define P2S_F   19200        //   p2s 128
#define TS_F    19328        //   ts 80
#define QR_F    19408        //   qraw 160
#define FM_F    19568        //   fms 16
// persistent
#define SS_F    26400        // S [125][10] = 1250
#define B1S_F   27650        // 80
#define W2S_F   27730        // 690
#define RED_F   28420        // 32
#define SC_F    28452        // 2
#define CORR_F  28456        // 32
#define CM_F    28488        // 16
#define SM_FLOATS 28504

// ---------------------------------------------------------------------------
// Threefry-2x32 (JAX partitionable) — bit-exact since R1
// ---------------------------------------------------------------------------
__device__ __forceinline__ void threefry2x32(uint32_t k0, uint32_t k1,
                                             uint32_t c0, uint32_t c1,
                                             uint32_t& y0, uint32_t& y1)
{
    uint32_t ks2 = k0 ^ k1 ^ 0x1BD11BDAu;
    uint32_t x0 = c0 + k0, x1 = c1 + k1;
#define TF_RND(r) { x0 += x1; x1 = (x1 << (r)) | (x1 >> (32 - (r))); x1 ^= x0; }
    TF_RND(13) TF_RND(15) TF_RND(26) TF_RND(6)  x0 += k1;  x1 += ks2 + 1u;
    TF_RND(17) TF_RND(29) TF_RND(16) TF_RND(24) x0 += ks2; x1 += k0  + 2u;
    TF_RND(13) TF_RND(15) TF_RND(26) TF_RND(6)  x0 += k0;  x1 += k1  + 3u;
    TF_RND(17) TF_RND(29) TF_RND(16) TF_RND(24) x0 += k1;  x1 += ks2 + 4u;
    TF_RND(13) TF_RND(15) TF_RND(26) TF_RND(6)  x0 += ks2; x1 += k0  + 5u;
#undef TF_RND
    y0 = x0; y1 = x1;
}
__device__ __forceinline__ float jax_unit_uniform(uint32_t f)
{
    uint32_t y0, y1;
    threefry2x32(0u, 42u, 0u, f, y0, y1);
    uint32_t bits = y0 ^ y1;
    float v = __uint_as_float((bits >> 9) | 0x3f800000u) - 1.0f;
    return (v == 0.0f) ? 1.17549435e-38f : v;
}

// ---------------------------------------------------------------------------
// Stage A inner loop, NJ = columns per thread (warp-uniform 4 or 5), float4.
// ---------------------------------------------------------------------------
template<int NJ>
__device__ __forceinline__ void stageA_loop(const float4* __restrict__ Hs4,
                                            const float4* __restrict__ W1t4,
                                            int tx, int ty, float acc[4][5])
{
#pragma unroll
    for (int i = 0; i < 4; ++i)
#pragma unroll
        for (int j = 0; j < NJ; ++j) acc[i][j] = 0.0f;

#pragma unroll 1
    for (int kq = 0; kq < 32; ++kq) {
        float4 h4[4], w4[NJ];
#pragma unroll
        for (int i = 0; i < 4; ++i) h4[i] = Hs4[(tx + 32 * i) * HS_LD4 + kq];
#pragma unroll
        for (int j = 0; j < NJ; ++j) w4[j] = W1t4[(ty + 16 * j) * W1T_LD4 + kq];
#pragma unroll
        for (int i = 0; i < 4; ++i)
#pragma unroll
            for (int j = 0; j < NJ; ++j) {
                acc[i][j] = fmaf(h4[i].x, w4[j].x, acc[i][j]);
                acc[i][j] = fmaf(h4[i].y, w4[j].y, acc[i][j]);
                acc[i][j] = fmaf(h4[i].z, w4[j].z, acc[i][j]);
                acc[i][j] = fmaf(h4[i].w, w4[j].w, acc[i][j]);
            }
    }
}

// ---------------------------------------------------------------------------
// Fused kernel: one block per graph, 512 threads, 2 CTAs/SM.
// ---------------------------------------------------------------------------
__global__ __launch_bounds__(512, 2) void ciflow_fused(
    const float* __restrict__ H,
    const int*   __restrict__ targets,
    const float* __restrict__ w1,  const float* __restrict__ b1,
    const float* __restrict__ w2,  const float* __restrict__ b2,
    const float* __restrict__ wf,  const float* __restrict__ bf,
    const float* __restrict__ p1,  const float* __restrict__ pb1,
    const float* __restrict__ p2,  const float* __restrict__ pb2,
    const float* __restrict__ ci,  const float* __restrict__ cia,
    float* __restrict__ out)
{
    extern __shared__ float sm[];
    float* Hs  = sm + HS_F;
    float* W1t = sm + W1T_F;
    float* As  = sm + AS_F;      // aliases W1t after stage A
    float* Ss  = sm + SS_F;
    float* b1s = sm + B1S_F;
    float* W2s = sm + W2S_F;

    const int g    = blockIdx.x;
    const int tid  = threadIdx.x;
    const int lane = tid & 31;
    const int wid  = tid >> 5;

    // ---- cooperative loads --------------------------------------------------
    const float*  Hg  = H + (size_t)g * NPG * D;
    const float4* Hg4 = (const float4*)Hg;
    for (int i4 = tid; i4 < NPG * D / 4; i4 += 512) {        // 4000 f4
        int m = i4 >> 5, k4 = i4 & 31;
        *(float4*)(Hs + m * HS_LD + 4 * k4) = Hg4[i4];
    }
    for (int idx = tid; idx < 3 * HS_LD; idx += 512)
        Hs[NPG * HS_LD + idx] = 0.0f;                        // zero rows 125..127
    for (int idx = tid; idx < 128 * 72; idx += 512) {        // W1^T, coalesced gmem
        int k = idx / 72, n = idx - k * 72;
        W1t[n * W1T_LD + k] = (n < SH) ? w1[k * SH + n] : 0.0f;
    }
    for (int idx = tid; idx < SH * NC; idx += 512) W2s[idx] = w2[idx];
    if (tid < 72) b1s[tid] = (tid < SH) ? b1[tid] : 0.0f;
    __syncthreads();

    // ---- stage A: A = relu(H @ w1 + b1), cols 0..68, float4 -----------------
    const int tx = tid & 31;
    const int ty = tid >> 5;
    const int jmax = (ty < 5) ? 5 : 4;
    float acc[4][5];
    const float4* Hs4  = (const float4*)(sm + HS_F);
    const float4* W1t4 = (const float4*)(sm + W1T_F);
    if (ty < 5) stageA_loop<5>(Hs4, W1t4, tx, ty, acc);
    else        stageA_loop<4>(Hs4, W1t4, tx, ty, acc);
    __syncthreads();            // all W1t reads done before aliasing to As

#pragma unroll
    for (int i = 0; i < 4; ++i) {
        int m = tx + 32 * i;
#pragma unroll
        for (int j = 0; j < 5; ++j)
            if (j < jmax) {
                int n = ty + 16 * j;
                As[m * AS_LD + n] = fmaxf(acc[i][j] + b1s[n], 0.0f);
            }
    }
    __syncthreads();

    // ---- stage Z: z = A @ w2 + b2, softmax -> S (2 threads per row) ---------
    if (tid < 256) {
        const int m    = tid >> 1;
        const int half = tid & 1;
        const int cb   = 5 * half;
        float z[5];
#pragma unroll
        for (int c = 0; c < 5; ++c) z[c] = __ldg(&b2[cb + c]);
        for (int n = 0; n < SH; ++n) {
            float a = As[m * AS_LD + n];
#pragma unroll
            for (int c = 0; c < 5; ++c) z[c] = fmaf(a, W2s[n * NC + cb + c], z[c]);
        }
        float mx = z[0];
#pragma unroll
        for (int c = 1; c < 5; ++c) mx = fmaxf(mx, z[c]);
        mx = fmaxf(mx, __shfl_xor_sync(0xffffffffu, mx, 1));
        float ssum = 0.0f;
#pragma unroll
        for (int c = 0; c < 5; ++c) { z[c] = expf(z[c] - mx); ssum += z[c]; }
        ssum += __shfl_xor_sync(0xffffffffu, ssum, 1);
        float inv = 1.0f / ssum;
        if (m < NPG) {
            float* srow = &Ss[m * NC + cb];
            float* gout = out + S_OFF + ((size_t)g * NPG + m) * NC + cb;
#pragma unroll
            for (int c = 0; c < 5; ++c) {
                float s = z[c] * inv;
                srow[c] = s;
                gout[c] = s;
            }
        }
    }
    __syncthreads();

    // ---- stage E: E[c][d] = sum_m S[m][c] H[m][d]; H from smem --------------
    float* Es  = sm + ES_F;
    float* p1s = sm + P1S_F;
    float* p2s = sm + P2S_F;
    {
        float pf[2];
#pragma unroll
        for (int r = 0; r < 2; ++r) pf[r] = __ldg(&p1[tid + 512 * r]);
        float pf2 = (tid < 128) ? __ldg(&p2[tid]) : 0.0f;

        const int d   = tid & 127;
        const int cg  = tid >> 7;
        const int c0  = (cg < 2) ? 3 * cg : 6 + 2 * (cg - 2);
        const int cnt = (cg < 2) ? 3 : 2;
        float e[3] = {0.f, 0.f, 0.f};
#pragma unroll 5
        for (int m = 0; m < NPG; ++m) {
            float h = Hs[m * HS_LD + d];
#pragma unroll
            for (int j = 0; j < 3; ++j)
                if (j < cnt) e[j] = fmaf(Ss[m * NC + c0 + j], h, e[j]);
        }
        float* Eout = out + E_OFF + (size_t)g * (NC * D);
#pragma unroll
        for (int j = 0; j < 3; ++j)
            if (j < cnt) {
                Eout[(c0 + j) * D + d] = e[j];
                Es[(c0 + j) * D + d]   = e[j];
            }
#pragma unroll
        for (int r = 0; r < 2; ++r) p1s[tid + 512 * r] = pf[r];
        if (tid < 128) p2s[tid] = pf2;
    }
    __syncthreads();

    // ======================= fused downstream ================================
    float* ts    = sm + TS_F;
    float* qraw  = sm + QR_F;
    float* fms   = sm + FM_F;
    float* red   = sm + RED_F;
    float* sc    = sm + SC_F;
    float* corrs = sm + CORR_F;
    float* cmask = sm + CM_F;

    // ---- epoch 1: pred1 partials --------------------------------------------
    float s0 = 0.f, s1 = 0.f;
#pragma unroll
    for (int r = 0; r < 3; ++r) {
        int i = tid + 512 * r;
        if (i < 1280) {
            float e = Es[i];
            float2 w = __ldg((const float2*)(wf + 2 * i));
            s0 = fmaf(e, w.x, s0);
            s1 = fmaf(e, w.y, s1);
        }
    }
#pragma unroll
    for (int off = 16; off; off >>= 1) {
        s0 += __shfl_down_sync(0xffffffffu, s0, off);
        s1 += __shfl_down_sync(0xffffffffu, s1, off);
    }
    if (lane == 0) { red[wid * 2] = s0; red[wid * 2 + 1] = s1; }
    __syncthreads();

    // ---- epoch 2: sampling (tid 0) | corr (32..63) | Q-hidden (192..511) ----
    if (tid == 0) {
        float z0 = bf[0], z1 = bf[1];
#pragma unroll
        for (int w = 0; w < 16; ++w) { z0 += red[2 * w]; z1 += red[2 * w + 1]; }
        out[P1_OFF + g * 2 + 0] = z0;
        out[P1_OFF + g * 2 + 1] = z1;
        float mx = fmaxf(z0, z1);
        float e0 = expf(z0 - mx), e1 = expf(z1 - mx);
        float inv = 1.0f / (e0 + e1);
        float pp0 = e0 * inv, pp1 = e1 * inv;

        float u0 = jax_unit_uniform(2u * g);
        float u1 = jax_unit_uniform(2u * g + 1u);
        float l0 = logf(pp0 + 1e-12f) - logf(-logf(u0));
        float l1 = logf(pp1 + 1e-12f) - logf(-logf(u1));
        int sample = (l1 > l0) ? 1 : 0;

        out[IND_OFF + g] = (sample == targets[g]) ? 1.0f : 0.0f;
        sc[0] = pp0 + ((sample == 0) ? (1.0f - pp0) : -pp0);
        sc[1] = pp1 + ((sample == 1) ? (1.0f - pp1) : -pp1);
    }

    if (tid >= 32 && tid < 64) {     // correlation [2][16]
        int t = tid - 32;
        int c = t >> 4, f = t & 15;
        float a0 = __ldg(&ci[f]), a1 = __ldg(&ci[16 + f]);
        float m = fmaxf(a0, a1);
        float e0 = expf(a0 - m), e1 = expf(a1 - m);
        float colv = ((c == 0) ? e0 : e1) / (e0 + e1);
        float rm = -1e30f;
        for (int ff = 0; ff < 16; ++ff) rm = fmaxf(rm, __ldg(&cia[c * 16 + ff]));
        float rs = 0.f;
        for (int ff = 0; ff < 16; ++ff) rs += expf(__ldg(&cia[c * 16 + ff]) - rm);
        corrs[c * 16 + f] = colv * (expf(__ldg(&cia[c * 16 + f]) - rm) / rs);
    }

    if (tid >= 192) {                // Q hidden, 4-way k-split: 80 units x 4
        int t  = tid - 192;
        int u  = t >> 2, ks = t & 3;
        int c  = u >> 3, j = u & 7;
        float a = 0.0f;
        const float* ec = Es + c * 128 + 32 * ks;
        const float* pj = p1s + (32 * ks) * 8 + j;
#pragma unroll 8
        for (int k = 0; k < 32; ++k) a = fmaf(ec[k], pj[8 * k], a);
        a += __shfl_down_sync(0xffffffffu, a, 2);
        a += __shfl_down_sync(0xffffffffu, a, 1);
        if (ks == 0) ts[u] = fmaxf(a + __ldg(&pb1[j]), 0.0f);
    }
    __syncthreads();

    // ---- epoch 3: cmask (tid<16) | Q output (160..319) ----------------------
    if (tid < 16) cmask[tid] = sc[0] * corrs[tid] + sc[1] * corrs[16 + tid];

    if (tid >= 160 && tid < 320) {
        int t = tid - 160;
        int c = t >> 4, f = t & 15;
        float a = __ldg(&pb2[f]);
#pragma unroll
        for (int j = 0; j < 8; ++j) a = fmaf(ts[c * 8 + j], p2s[j * 16 + f], a);
        qraw[t] = a;
    }
    __syncthreads();

    // ---- epoch 4: Q softmax + feature mask, 160 threads, shfl ---------------
    if (tid < 160) {
        int c = tid >> 4, f = tid & 15;
        float v = qraw[tid];
        float mx = v;
#pragma unroll
        for (int off = 8; off; off >>= 1)
            mx = fmaxf(mx, __shfl_xor_sync(0xffffffffu, mx, off));
        float e = expf(v - mx);
        float ssum = e;
#pragma unroll
        for (int off = 8; off; off >>= 1)
            ssum += __shfl_xor_sync(0xffffffffu, ssum, off);
        float q = e / ssum;
        out[Q_OFF + (size_t)g * 160 + c * 16 + f] = q;
        float fm = q * cmask[f];
#pragma unroll
        for (int off = 8; off; off >>= 1)
            fm += __shfl_xor_sync(0xffffffffu, fm, off);
        if (f == 0) fms[c] = fm;
    }
    __syncthreads();

    // ---- epoch 5: pred2 ------------------------------------------------------
    s0 = 0.f; s1 = 0.f;
#pragma unroll
    for (int r = 0; r < 3; ++r) {
        int i = tid + 512 * r;
        if (i < 1280) {
            float e = fms[i >> 7] * Es[i];
            float2 w = __ldg((const float2*)(wf + 2 * i));
            s0 = fmaf(e, w.x, s0);
            s1 = fmaf(e, w.y, s1);
        }
    }
#pragma unroll
    for (int off = 16; off; off >>= 1) {
        s0 += __shfl_down_sync(0xffffffffu, s0, off);
        s1 += __shfl_down_sync(0xffffffffu, s1, off);
    }
    if (lane == 0) { red[wid * 2] = s0; red[wid * 2 + 1] = s1; }
    __syncthreads();
    if (tid == 0) {
        float z0 = bf[0], z1 = bf[1];
#pragma unroll
        for (int w = 0; w < 16; ++w) { z0 += red[2 * w]; z1 += red[2 * w + 1]; }
        out[P2_OFF + g * 2 + 0] = z0;
        out[P2_OFF + g * 2 + 1] = z1;
    }
}

// ---------------------------------------------------------------------------
extern "C" void kernel_launch(void* const* d_in, const int* in_sizes, int n_in,
                              void* d_out, int out_size)
{
    const float* H   = (const float*)d_in[0];
    const int*   tgt = (const int*)  d_in[2];
    const float* w1  = (const float*)d_in[3];
    const float* b1  = (const float*)d_in[4];
    const float* w2  = (const float*)d_in[5];
    const float* b2  = (const float*)d_in[6];
    const float* wf  = (const float*)d_in[7];
    const float* bf  = (const float*)d_in[8];
    const float* p1  = (const float*)d_in[9];
    const float* pb1 = (const float*)d_in[10];
    const float* p2  = (const float*)d_in[11];
    const float* pb2 = (const float*)d_in[12];
    const float* ci  = (const float*)d_in[13];
    const float* cia = (const float*)d_in[14];
    float* out = (float*)d_out;

    const int smem = SM_FLOATS * 4;
    static bool attr_set = false;
    if (!attr_set) {
        cudaFuncSetAttribute(ciflow_fused,
                             cudaFuncAttributeMaxDynamicSharedMemorySize, smem);
        attr_set = true;
    }

    ciflow_fused<<<NGRAPH, 512, smem>>>(H, tgt, w1, b1, w2, b2, wf, bf,
                                        p1, pb1, p2, pb2, ci, cia, out);
}

// round 8
// speedup vs baseline: 1.8557x; 1.2838x over previous
#include <cuda_runtime.h>
#include <cuda_bf16.h>
#include <cstdint>

// Problem constants
#define NGRAPH 512
#define NPG    125
#define D      128
#define SH     69
#define NC     10

// d_out float offsets
#define P1_OFF  0
#define P2_OFF  1024
#define IND_OFF 2048
#define S_OFF   2560
#define E_OFF   642560
#define Q_OFF   1297920

// ---- smem layout (bytes) ---------------------------------------------------
#define HHI_B   0          // H hi  [128][128] bf16, XOR-swizzled (32768)
#define HLO_B   32768      // H lo  (32768)
#define WHI_B   65536      // W1^T hi [72][128] bf16 (18432); later Zred alias
#define WLO_B   83968      // W1^T lo (18432); later Es/p1s/p2s/ts/qraw alias
// aliases (after MMA / Z)
#define ZRED_B  65536      // Zred [2][128][11] f32 = 11264
#define ES_B    83968      // Es 1280 f
#define P1S_B   89088      // 1024 f
#define P2S_B   93184      // 128 f
#define TS_B    93696      // 80 f
#define QR_B    94016      // 160 f
// persistent
#define SS_B    102400     // S [125][10] f32 (5000)
#define B1S_B   107400     // 72 f (288)
#define W2P_B   107696     // W2 padded [72][12] f32 (3456), 16B-aligned
#define RED_B   111152     // 32 f
#define SC_B    111280     // 2 f
#define CORR_B  111288     // 32 f
#define CM_B    111416     // 16 f
#define FMS_B   111480     // 16 f
#define SMEM_TOTAL 111552  // ~108.9 KB -> 2 CTAs/SM

// ---------------------------------------------------------------------------
__device__ __forceinline__ uint32_t smem_u32(const void* p) {
    uint32_t a;
    asm("{ .reg .u64 t; cvta.to.shared.u64 t, %1; cvt.u32.u64 %0, t; }"
        : "=r"(a) : "l"(p));
    return a;
}
__device__ __forceinline__ void ldsm4(uint32_t a, uint32_t& r0, uint32_t& r1,
                                      uint32_t& r2, uint32_t& r3) {
    asm volatile("ldmatrix.sync.aligned.m8n8.x4.shared.b16 {%0,%1,%2,%3}, [%4];"
                 : "=r"(r0), "=r"(r1), "=r"(r2), "=r"(r3) : "r"(a));
}
__device__ __forceinline__ void ldsm2(uint32_t a, uint32_t& r0, uint32_t& r1) {
    asm volatile("ldmatrix.sync.aligned.m8n8.x2.shared.b16 {%0,%1}, [%2];"
                 : "=r"(r0), "=r"(r1) : "r"(a));
}
#define MMA(ac, a0, a1, a2, a3, b0, b1) \
    asm volatile("mma.sync.aligned.m16n8k16.row.col.f32.bf16.bf16.f32 " \
                 "{%0,%1,%2,%3}, {%4,%5,%6,%7}, {%8,%9}, {%0,%1,%2,%3};" \
                 : "+f"((ac)[0]), "+f"((ac)[1]), "+f"((ac)[2]), "+f"((ac)[3]) \
                 : "r"(a0), "r"(a1), "r"(a2), "r"(a3), "r"(b0), "r"(b1))

// element (row, bf16-pair p) -> swizzled byte offset (row stride 256B)
__device__ __forceinline__ uint32_t sw_off(int row, int p) {
    return (uint32_t)row * 256u + (uint32_t)(((p >> 2) ^ (row & 7)) << 4)
         + (uint32_t)((p & 3) << 2);
}

// ---------------------------------------------------------------------------
// Threefry-2x32 (JAX partitionable) — bit-exact since R1
// ---------------------------------------------------------------------------
__device__ __forceinline__ void threefry2x32(uint32_t k0, uint32_t k1,
                                             uint32_t c0, uint32_t c1,
                                             uint32_t& y0, uint32_t& y1)
{
    uint32_t ks2 = k0 ^ k1 ^ 0x1BD11BDAu;
    uint32_t x0 = c0 + k0, x1 = c1 + k1;
#define TF_RND(r) { x0 += x1; x1 = (x1 << (r)) | (x1 >> (32 - (r))); x1 ^= x0; }
    TF_RND(13) TF_RND(15) TF_RND(26) TF_RND(6)  x0 += k1;  x1 += ks2 + 1u;
    TF_RND(17) TF_RND(29) TF_RND(16) TF_RND(24) x0 += ks2; x1 += k0  + 2u;
    TF_RND(13) TF_RND(15) TF_RND(26) TF_RND(6)  x0 += k0;  x1 += k1  + 3u;
    TF_RND(17) TF_RND(29) TF_RND(16) TF_RND(24) x0 += k1;  x1 += ks2 + 4u;
    TF_RND(13) TF_RND(15) TF_RND(26) TF_RND(6)  x0 += ks2; x1 += k0  + 5u;
#undef TF_RND
    y0 = x0; y1 = x1;
}
__device__ __forceinline__ float jax_unit_uniform(uint32_t f)
{
    uint32_t y0, y1;
    threefry2x32(0u, 42u, 0u, f, y0, y1);
    uint32_t bits = y0 ^ y1;
    float v = __uint_as_float((bits >> 9) | 0x3f800000u) - 1.0f;
    return (v == 0.0f) ? 1.17549435e-38f : v;
}

// split f32 -> (hi, lo) bf16 pair packed as u32 x2
__device__ __forceinline__ void bf16_split2(float x0, float x1,
                                            uint32_t& hi, uint32_t& lo)
{
    __nv_bfloat16 h0 = __float2bfloat16(x0);
    __nv_bfloat16 h1 = __float2bfloat16(x1);
    __nv_bfloat16 l0 = __float2bfloat16(x0 - __bfloat162float(h0));
    __nv_bfloat16 l1 = __float2bfloat16(x1 - __bfloat162float(h1));
    hi = (uint32_t)__bfloat16_as_ushort(h0)
       | ((uint32_t)__bfloat16_as_ushort(h1) << 16);
    lo = (uint32_t)__bfloat16_as_ushort(l0)
       | ((uint32_t)__bfloat16_as_ushort(l1) << 16);
}

// ---------------------------------------------------------------------------
// Fused kernel: one block per graph, 512 threads, 2 CTAs/SM, HMMA stage A.
// ---------------------------------------------------------------------------
__global__ __launch_bounds__(512, 2) void ciflow_fused(
    const float* __restrict__ H,
    const int*   __restrict__ targets,
    const float* __restrict__ w1,  const float* __restrict__ b1,
    const float* __restrict__ w2,  const float* __restrict__ b2,
    const float* __restrict__ wf,  const float* __restrict__ bf,
    const float* __restrict__ p1,  const float* __restrict__ pb1,
    const float* __restrict__ p2,  const float* __restrict__ pb2,
    const float* __restrict__ ci,  const float* __restrict__ cia,
    float* __restrict__ out)
{
    extern __shared__ char smc[];
    const uint32_t sb = smem_u32(smc);

    float* Ss  = (float*)(smc + SS_B);
    float* b1s = (float*)(smc + B1S_B);
    float* W2p = (float*)(smc + W2P_B);
    float* Zrd = (float*)(smc + ZRED_B);

    const int g    = blockIdx.x;
    const int tid  = threadIdx.x;
    const int lane = tid & 31;
    const int wid  = tid >> 5;

    // ---- convert phase: f32 -> bf16 hi/lo into swizzled smem ---------------
    const float*  Hg  = H + (size_t)g * NPG * D;
    const float2* Hg2 = (const float2*)Hg;
    for (int i = tid; i < NPG * 64; i += 512) {            // 8000 pairs
        int m = i >> 6, p = i & 63;
        float2 v = Hg2[i];
        uint32_t hi, lo;
        bf16_split2(v.x, v.y, hi, lo);
        uint32_t o = sw_off(m, p);
        *(uint32_t*)(smc + HHI_B + o) = hi;
        *(uint32_t*)(smc + HLO_B + o) = lo;
    }
    for (int i = tid; i < 3 * 64; i += 512) {              // zero rows 125..127
        int m = NPG + (i >> 6), p = i & 63;
        uint32_t o = sw_off(m, p);
        *(uint32_t*)(smc + HHI_B + o) = 0u;
        *(uint32_t*)(smc + HLO_B + o) = 0u;
    }
    for (int i = tid; i < 72 * 64; i += 512) {             // W1^T (n-major)
        int p = i / 72, n = i - p * 72;
        float x0 = (n < SH) ? w1[(2 * p)     * SH + n] : 0.0f;
        float x1 = (n < SH) ? w1[(2 * p + 1) * SH + n] : 0.0f;
        uint32_t hi, lo;
        bf16_split2(x0, x1, hi, lo);
        uint32_t o = sw_off(n, p);
        *(uint32_t*)(smc + WHI_B + o) = hi;
        *(uint32_t*)(smc + WLO_B + o) = lo;
    }
    if (tid < 72) b1s[tid] = (tid < SH) ? b1[tid] : 0.0f;
    for (int i = tid; i < 72 * 12; i += 512) {             // W2 padded [72][12]
        int r = i / 12, c = i - r * 12;
        W2p[i] = (r < SH && c < NC) ? w2[r * NC + c] : 0.0f;
    }
    __syncthreads();

    // ---- stage A via mma.sync: A = H @ W1t^T, 3-term bf16 compensation -----
    const int mtile = wid >> 1;
    const int half  = wid & 1;
    // A ldmatrix lane addressing (tiles: [rlo,klo],[rhi,klo],[rlo,khi],[rhi,khi])
    const int tA = lane >> 3, rA = lane & 7;
    const int mRow = mtile * 16 + ((tA & 1) << 3) + rA;
    const uint32_t aBase = sb + HHI_B + (uint32_t)mRow * 256u;
    const int aSw = mRow & 7, aCo = tA >> 1;
    // B x4 (tiles: [p,klo],[p,khi],[p+1,klo],[p+1,khi])
    const int nR4 = ((tA >> 1) << 3) + rA;
    const uint32_t b4Base = sb + WHI_B + (uint32_t)nR4 * 256u;
    const int b4Sw = rA, b4Co = tA & 1;
    // B x2 (lanes 0..15 matter)
    const int t2 = (lane >> 3) & 1;
    const uint32_t b2Base = sb + WHI_B + (uint32_t)rA * 256u;
    const int b2Co = t2;

    float acc[5][4];
#pragma unroll
    for (int t = 0; t < 5; ++t)
#pragma unroll
        for (int c = 0; c < 4; ++c) acc[t][c] = 0.0f;

#pragma unroll 2
    for (int s = 0; s < 8; ++s) {
        const int c2 = 2 * s;
        uint32_t ah0, ah1, ah2, ah3, al0, al1, al2, al3;
        uint32_t aAddr = aBase + (uint32_t)(((c2 + aCo) ^ aSw) << 4);
        ldsm4(aAddr,         ah0, ah1, ah2, ah3);
        ldsm4(aAddr + 32768, al0, al1, al2, al3);

        if (half == 0) {
            uint32_t bh0, bh1, bh2, bh3, bl0, bl1, bl2, bl3;
            uint32_t bA = b4Base + (uint32_t)(((c2 + b4Co) ^ b4Sw) << 4);
            ldsm4(bA,         bh0, bh1, bh2, bh3);          // tiles 0,1
            ldsm4(bA + 18432, bl0, bl1, bl2, bl3);
            MMA(acc[0], ah0, ah1, ah2, ah3, bh0, bh1);
            MMA(acc[0], ah0, ah1, ah2, ah3, bl0, bl1);
            MMA(acc[0], al0, al1, al2, al3, bh0, bh1);
            MMA(acc[1], ah0, ah1, ah2, ah3, bh2, bh3);
            MMA(acc[1], ah0, ah1, ah2, ah3, bl2, bl3);
            MMA(acc[1], al0, al1, al2, al3, bh2, bh3);
            bA += 2u * 2048u;                               // tiles 2,3
            ldsm4(bA,         bh0, bh1, bh2, bh3);
            ldsm4(bA + 18432, bl0, bl1, bl2, bl3);
            MMA(acc[2], ah0, ah1, ah2, ah3, bh0, bh1);
            MMA(acc[2], ah0, ah1, ah2, ah3, bl0, bl1);
            MMA(acc[2], al0, al1, al2, al3, bh0, bh1);
            MMA(acc[3], ah0, ah1, ah2, ah3, bh2, bh3);
            MMA(acc[3], ah0, ah1, ah2, ah3, bl2, bl3);
            MMA(acc[3], al0, al1, al2, al3, bh2, bh3);
            uint32_t bB = b2Base + 4u * 2048u
                        + (uint32_t)(((c2 + b2Co) ^ rA) << 4);   // tile 4
            ldsm2(bB,         bh0, bh1);
            ldsm2(bB + 18432, bl0, bl1);
            MMA(acc[4], ah0, ah1, ah2, ah3, bh0, bh1);
            MMA(acc[4], ah0, ah1, ah2, ah3, bl0, bl1);
            MMA(acc[4], al0, al1, al2, al3, bh0, bh1);
        } else {
            uint32_t bh0, bh1, bh2, bh3, bl0, bl1, bl2, bl3;
            uint32_t bA = b4Base + 5u * 2048u
                        + (uint32_t)(((c2 + b4Co) ^ b4Sw) << 4); // tiles 5,6
            ldsm4(bA,         bh0, bh1, bh2, bh3);
            ldsm4(bA + 18432, bl0, bl1, bl2, bl3);
            MMA(acc[0], ah0, ah1, ah2, ah3, bh0, bh1);
            MMA(acc[0], ah0, ah1, ah2, ah3, bl0, bl1);
            MMA(acc[0], al0, al1, al2, al3, bh0, bh1);
            MMA(acc[1], ah0, ah1, ah2, ah3, bh2, bh3);
            MMA(acc[1], ah0, ah1, ah2, ah3, bl2, bl3);
            MMA(acc[1], al0, al1, al2, al3, bh2, bh3);
            bA += 2u * 2048u;                                // tiles 7,8
            ldsm4(bA,         bh0, bh1, bh2, bh3);
            ldsm4(bA + 18432, bl0, bl1, bl2, bl3);
            MMA(acc[2], ah0, ah1, ah2, ah3, bh0, bh1);
            MMA(acc[2], ah0, ah1, ah2, ah3, bl0, bl1);
            MMA(acc[2], al0, al1, al2, al3, bh0, bh1);
            MMA(acc[3], ah0, ah1, ah2, ah3, bh2, bh3);
            MMA(acc[3], ah0, ah1, ah2, ah3, bl2, bl3);
            MMA(acc[3], al0, al1, al2, al3, bh2, bh3);
        }
    }

    // ---- register epilogue: relu + b1, partial Z = A @ W2 -------------------
    const int nOff = 2 * (lane & 3);
    const int r0   = mtile * 16 + (lane >> 2);
    const int ntB  = half ? 5 : 0;
    const int ntC  = half ? 4 : 5;
    float z0[10], z1[10];
#pragma unroll
    for (int c = 0; c < 10; ++c) { z0[c] = 0.f; z1[c] = 0.f; }
#pragma unroll
    for (int ti = 0; ti < 5; ++ti) {
        if (ti < ntC) {
            int n = (ntB + ti) * 8 + nOff;
            float a00 = fmaxf(acc[ti][0] + b1s[n],     0.0f);
            float a01 = fmaxf(acc[ti][1] + b1s[n + 1], 0.0f);
            float a10 = fmaxf(acc[ti][2] + b1s[n],     0.0f);
            float a11 = fmaxf(acc[ti][3] + b1s[n + 1], 0.0f);
            const float* w2r0 = W2p + n * 12;
            const float* w2r1 = w2r0 + 12;
#pragma unroll
            for (int c = 0; c < 10; ++c) {
                float wa = w2r0[c], wb = w2r1[c];
                z0[c] = fmaf(a00, wa, fmaf(a01, wb, z0[c]));
                z1[c] = fmaf(a10, wa, fmaf(a11, wb, z1[c]));
            }
        }
    }
#pragma unroll
    for (int off = 1; off <= 2; off <<= 1) {
#pragma unroll
        for (int c = 0; c < 10; ++c) {
            z0[c] += __shfl_xor_sync(0xffffffffu, z0[c], off);
            z1[c] += __shfl_xor_sync(0xffffffffu, z1[c], off);
        }
    }
    __syncthreads();           // all ldmatrix reads of W region done
    if ((lane & 3) == 0) {
#pragma unroll
        for (int c = 0; c < 10; ++c) {
            Zrd[(half * 128 + r0) * 11 + c]     = z0[c];
            Zrd[(half * 128 + r0 + 8) * 11 + c] = z1[c];
        }
    }
    __syncthreads();

    // ---- Z combine + softmax -> S (threads 0..127); others prefetch p1/p2 --
    float* p1s = (float*)(smc + P1S_B);
    float* p2s = (float*)(smc + P2S_B);
    if (tid < 128) {
        int m = tid;
        float z[10];
#pragma unroll
        for (int c = 0; c < 10; ++c)
            z[c] = Zrd[m * 11 + c] + Zrd[(128 + m) * 11 + c] + __ldg(&b2[c]);
        if (m < NPG) {
            float mx = z[0];
#pragma unroll
            for (int c = 1; c < 10; ++c) mx = fmaxf(mx, z[c]);
            float ssum = 0.0f;
#pragma unroll
            for (int c = 0; c < 10; ++c) { z[c] = expf(z[c] - mx); ssum += z[c]; }
            float inv = 1.0f / ssum;
            float* gout = out + S_OFF + ((size_t)g * NPG + m) * NC;
#pragma unroll
            for (int c = 0; c < 10; ++c) {
                float s = z[c] * inv;
                Ss[m * NC + c] = s;
                gout[c] = s;
            }
        }
    } else {
        int t = tid - 128;
        for (int i = t; i < 1024; i += 384) p1s[i] = __ldg(&p1[i]);
        if (t < 128) p2s[t] = __ldg(&p2[t]);
    }
    __syncthreads();

    // ---- stage E: E[c][d] = sum_m S[m][c] H[m][d]; H from L2 (f32) ----------
    float* Es = (float*)(smc + ES_B);
    {
        const int d   = tid & 127;
        const int cg  = tid >> 7;
        const int c0  = (cg < 2) ? 3 * cg : 6 + 2 * (cg - 2);
        const int cnt = (cg < 2) ? 3 : 2;
        float e[3] = {0.f, 0.f, 0.f};
#pragma unroll 5
        for (int m = 0; m < NPG; ++m) {
            float h = __ldg(&Hg[m * D + d]);
#pragma unroll
            for (int j = 0; j < 3; ++j)
                if (j < cnt) e[j] = fmaf(Ss[m * NC + c0 + j], h, e[j]);
        }
        float* Eout = out + E_OFF + (size_t)g * (NC * D);
#pragma unroll
        for (int j = 0; j < 3; ++j)
            if (j < cnt) {
                Eout[(c0 + j) * D + d] = e[j];
                Es[(c0 + j) * D + d]   = e[j];
            }
    }
    __syncthreads();

    // ======================= fused downstream (R7 epochs) ====================
    float* ts    = (float*)(smc + TS_B);
    float* qraw  = (float*)(smc + QR_B);
    float* fms   = (float*)(smc + FMS_B);
    float* red   = (float*)(smc + RED_B);
    float* sc    = (float*)(smc + SC_B);
    float* corrs = (float*)(smc + CORR_B);
    float* cmask = (float*)(smc + CM_B);

    // epoch 1: pred1 partials
    float s0 = 0.f, s1 = 0.f;
#pragma unroll
    for (int r = 0; r < 3; ++r) {
        int i = tid + 512 * r;
        if (i < 1280) {
            float e = Es[i];
            float2 w = __ldg((const float2*)(wf + 2 * i));
            s0 = fmaf(e, w.x, s0);
            s1 = fmaf(e, w.y, s1);
        }
    }
#pragma unroll
    for (int off = 16; off; off >>= 1) {
        s0 += __shfl_down_sync(0xffffffffu, s0, off);
        s1 += __shfl_down_sync(0xffffffffu, s1, off);
    }
    if (lane == 0) { red[wid * 2] = s0; red[wid * 2 + 1] = s1; }
    __syncthreads();

    // epoch 2: sampling | correlation | Q hidden
    if (tid == 0) {
        float z0v = bf[0], z1v = bf[1];
#pragma unroll
        for (int w = 0; w < 16; ++w) { z0v += red[2 * w]; z1v += red[2 * w + 1]; }
        out[P1_OFF + g * 2 + 0] = z0v;
        out[P1_OFF + g * 2 + 1] = z1v;
        float mx = fmaxf(z0v, z1v);
        float e0 = expf(z0v - mx), e1 = expf(z1v - mx);
        float inv = 1.0f / (e0 + e1);
        float pp0 = e0 * inv, pp1 = e1 * inv;

        float u0 = jax_unit_uniform(2u * g);
        float u1 = jax_unit_uniform(2u * g + 1u);
        float l0 = logf(pp0 + 1e-12f) - logf(-logf(u0));
        float l1 = logf(pp1 + 1e-12f) - logf(-logf(u1));
        int sample = (l1 > l0) ? 1 : 0;

        out[IND_OFF + g] = (sample == targets[g]) ? 1.0f : 0.0f;
        sc[0] = pp0 + ((sample == 0) ? (1.0f - pp0) : -pp0);
        sc[1] = pp1 + ((sample == 1) ? (1.0f - pp1) : -pp1);
    }

    if (tid >= 32 && tid < 64) {
        int t = tid - 32;
        int c = t >> 4, f = t & 15;
        float a0 = __ldg(&ci[f]), a1 = __ldg(&ci[16 + f]);
        float m = fmaxf(a0, a1);
        float e0 = expf(a0 - m), e1 = expf(a1 - m);
        float colv = ((c == 0) ? e0 : e1) / (e0 + e1);
        float rm = -1e30f;
        for (int ff = 0; ff < 16; ++ff) rm = fmaxf(rm, __ldg(&cia[c * 16 + ff]));
        float rs = 0.f;
        for (int ff = 0; ff < 16; ++ff) rs += expf(__ldg(&cia[c * 16 + ff]) - rm);
        corrs[c * 16 + f] = colv * (expf(__ldg(&cia[c * 16 + f]) - rm) / rs);
    }

    if (tid >= 192) {                // Q hidden, 4-way k-split
        int t  = tid - 192;
        int u  = t >> 2, ks = t & 3;
        int c  = u >> 3, j = u & 7;
        float a = 0.0f;
        const float* ec = Es + c * 128 + 32 * ks;
        const float* pj = p1s + (32 * ks) * 8 + j;
#pragma unroll 8
        for (int k = 0; k < 32; ++k) a = fmaf(ec[k], pj[8 * k], a);
        a += __shfl_down_sync(0xffffffffu, a, 2);
        a += __shfl_down_sync(0xffffffffu, a, 1);
        if (ks == 0) ts[u] = fmaxf(a + __ldg(&pb1[j]), 0.0f);
    }
    __syncthreads();

    // epoch 3: cmask | Q output
    if (tid < 16) cmask[tid] = sc[0] * corrs[tid] + sc[1] * corrs[16 + tid];

    if (tid >= 160 && tid < 320) {
        int t = tid - 160;
        int c = t >> 4, f = t & 15;
        float a = __ldg(&pb2[f]);
#pragma unroll
        for (int j = 0; j < 8; ++j) a = fmaf(ts[c * 8 + j], p2s[j * 16 + f], a);
        qraw[t] = a;
    }
    __syncthreads();

    // epoch 4: Q softmax + feature mask
    if (tid < 160) {
        int c = tid >> 4, f = tid & 15;
        float v = qraw[tid];
        float mx = v;
#pragma unroll
        for (int off = 8; off; off >>= 1)
            mx = fmaxf(mx, __shfl_xor_sync(0xffffffffu, mx, off));
        float e = expf(v - mx);
        float ssum = e;
#pragma unroll
        for (int off = 8; off; off >>= 1)
            ssum += __shfl_xor_sync(0xffffffffu, ssum, off);
        float q = e / ssum;
        out[Q_OFF + (size_t)g * 160 + c * 16 + f] = q;
        float fm = q * cmask[f];
#pragma unroll
        for (int off = 8; off; off >>= 1)
            fm += __shfl_xor_sync(0xffffffffu, fm, off);
        if (f == 0) fms[c] = fm;
    }
    __syncthreads();

    // epoch 5: pred2
    s0 = 0.f; s1 = 0.f;
#pragma unroll
    for (int r = 0; r < 3; ++r) {
        int i = tid + 512 * r;
        if (i < 1280) {
            float e = fms[i >> 7] * Es[i];
            float2 w = __ldg((const float2*)(wf + 2 * i));
            s0 = fmaf(e, w.x, s0);
            s1 = fmaf(e, w.y, s1);
        }
    }
#pragma unroll
    for (int off = 16; off; off >>= 1) {
        s0 += __shfl_down_sync(0xffffffffu, s0, off);
        s1 += __shfl_down_sync(0xffffffffu, s1, off);
    }
    if (lane == 0) { red[wid * 2] = s0; red[wid * 2 + 1] = s1; }
    __syncthreads();
    if (tid == 0) {
        float z0v = bf[0], z1v = bf[1];
#pragma unroll
        for (int w = 0; w < 16; ++w) { z0v += red[2 * w]; z1v += red[2 * w + 1]; }
        out[P2_OFF + g * 2 + 0] = z0v;
        out[P2_OFF + g * 2 + 1] = z1v;
    }
}

// ---------------------------------------------------------------------------
extern "C" void kernel_launch(void* const* d_in, const int* in_sizes, int n_in,
                              void* d_out, int out_size)
{
    const float* H   = (const float*)d_in[0];
    const int*   tgt = (const int*)  d_in[2];
    const float* w1  = (const float*)d_in[3];
    const float* b1  = (const float*)d_in[4];
    const float* w2  = (const float*)d_in[5];
    const float* b2  = (const float*)d_in[6];
    const float* wf  = (const float*)d_in[7];
    const float* bf  = (const float*)d_in[8];
    const float* p1  = (const float*)d_in[9];
    const float* pb1 = (const float*)d_in[10];
    const float* p2  = (const float*)d_in[11];
    const float* pb2 = (const float*)d_in[12];
    const float* ci  = (const float*)d_in[13];
    const float* cia = (const float*)d_in[14];
    float* out = (float*)d_out;

    static bool attr_set = false;
    if (!attr_set) {
        cudaFuncSetAttribute(ciflow_fused,
                             cudaFuncAttributeMaxDynamicSharedMemorySize, SMEM_TOTAL);
        attr_set = true;
    }

    ciflow_fused<<<NGRAPH, 512, SMEM_TOTAL>>>(H, tgt, w1, b1, w2, b2, wf, bf,
                                              p1, pb1, p2, pb2, ci, cia, out);
}

// round 9
// speedup vs baseline: 1.8904x; 1.0187x over previous
#include <cuda_runtime.h>
#include <cuda_bf16.h>
#include <cstdint>

// Problem constants
#define NGRAPH 512
#define NPG    125
#define D      128
#define SH     69
#define NC     10

// d_out float offsets
#define P1_OFF  0
#define P2_OFF  1024
#define IND_OFF 2048
#define S_OFF   2560
#define E_OFF   642560
#define Q_OFF   1297920

// ---- smem layout (bytes) ---------------------------------------------------
#define HHI_B   0          // H hi  [128][128] bf16, XOR-swizzled (32768) - live thru E
#define HLO_B   32768      // H lo  (32768) - live thru E
#define WHI_B   65536      // W1^T hi [72][128] bf16 (18432); later Zred alias
#define WLO_B   83968      // W1^T lo (18432); later Es/p1s/p2s/ts/qraw alias
// aliases (after MMA / Z)
#define ZRED_B  65536      // Zred [2][128][11] f32 = 11264
#define ES_B    83968      // Es 1280 f
#define P1S_B   89088      // 1024 f
#define P2S_B   93184      // 128 f
#define TS_B    93696      // 80 f
#define QR_B    94016      // 160 f
// persistent
#define SS_B    102400     // S [125][10] f32 (5000)
#define B1S_B   107400     // 72 f (288)
#define W2P_B   107696     // W2 padded [72][12] f32 (3456)
#define RED_B   111152     // 32 f
#define SC_B    111280     // 2 f
#define CORR_B  111288     // 32 f
#define CM_B    111416     // 16 f
#define FMS_B   111480     // 16 f
#define SMEM_TOTAL 111552  // ~108.9 KB -> 2 CTAs/SM

// ---------------------------------------------------------------------------
__device__ __forceinline__ uint32_t smem_u32(const void* p) {
    uint32_t a;
    asm("{ .reg .u64 t; cvta.to.shared.u64 t, %1; cvt.u32.u64 %0, t; }"
        : "=r"(a) : "l"(p));
    return a;
}
__device__ __forceinline__ void ldsm4(uint32_t a, uint32_t& r0, uint32_t& r1,
                                      uint32_t& r2, uint32_t& r3) {
    asm volatile("ldmatrix.sync.aligned.m8n8.x4.shared.b16 {%0,%1,%2,%3}, [%4];"
                 : "=r"(r0), "=r"(r1), "=r"(r2), "=r"(r3) : "r"(a));
}
__device__ __forceinline__ void ldsm2(uint32_t a, uint32_t& r0, uint32_t& r1) {
    asm volatile("ldmatrix.sync.aligned.m8n8.x2.shared.b16 {%0,%1}, [%2];"
                 : "=r"(r0), "=r"(r1) : "r"(a));
}
#define MMA(ac, a0, a1, a2, a3, b0, b1) \
    asm volatile("mma.sync.aligned.m16n8k16.row.col.f32.bf16.bf16.f32 " \
                 "{%0,%1,%2,%3}, {%4,%5,%6,%7}, {%8,%9}, {%0,%1,%2,%3};" \
                 : "+f"((ac)[0]), "+f"((ac)[1]), "+f"((ac)[2]), "+f"((ac)[3]) \
                 : "r"(a0), "r"(a1), "r"(a2), "r"(a3), "r"(b0), "r"(b1))

// element (row, bf16-pair p) -> swizzled byte offset (row stride 256B)
__device__ __forceinline__ uint32_t sw_off(int row, int p) {
    return (uint32_t)row * 256u + (uint32_t)(((p >> 2) ^ (row & 7)) << 4)
         + (uint32_t)((p & 3) << 2);
}

// ---------------------------------------------------------------------------
// Threefry-2x32 (JAX partitionable) — bit-exact since R1
// ---------------------------------------------------------------------------
__device__ __forceinline__ void threefry2x32(uint32_t k0, uint32_t k1,
                                             uint32_t c0, uint32_t c1,
                                             uint32_t& y0, uint32_t& y1)
{
    uint32_t ks2 = k0 ^ k1 ^ 0x1BD11BDAu;
    uint32_t x0 = c0 + k0, x1 = c1 + k1;
#define TF_RND(r) { x0 += x1; x1 = (x1 << (r)) | (x1 >> (32 - (r))); x1 ^= x0; }
    TF_RND(13) TF_RND(15) TF_RND(26) TF_RND(6)  x0 += k1;  x1 += ks2 + 1u;
    TF_RND(17) TF_RND(29) TF_RND(16) TF_RND(24) x0 += ks2; x1 += k0  + 2u;
    TF_RND(13) TF_RND(15) TF_RND(26) TF_RND(6)  x0 += k0;  x1 += k1  + 3u;
    TF_RND(17) TF_RND(29) TF_RND(16) TF_RND(24) x0 += k1;  x1 += ks2 + 4u;
    TF_RND(13) TF_RND(15) TF_RND(26) TF_RND(6)  x0 += ks2; x1 += k0  + 5u;
#undef TF_RND
    y0 = x0; y1 = x1;
}
__device__ __forceinline__ float jax_unit_uniform(uint32_t f)
{
    uint32_t y0, y1;
    threefry2x32(0u, 42u, 0u, f, y0, y1);
    uint32_t bits = y0 ^ y1;
    float v = __uint_as_float((bits >> 9) | 0x3f800000u) - 1.0f;
    return (v == 0.0f) ? 1.17549435e-38f : v;
}

// split f32 -> (hi, lo) bf16 pair packed as u32 x2
__device__ __forceinline__ void bf16_split2(float x0, float x1,
                                            uint32_t& hi, uint32_t& lo)
{
    __nv_bfloat16 h0 = __float2bfloat16(x0);
    __nv_bfloat16 h1 = __float2bfloat16(x1);
    __nv_bfloat16 l0 = __float2bfloat16(x0 - __bfloat162float(h0));
    __nv_bfloat16 l1 = __float2bfloat16(x1 - __bfloat162float(h1));
    hi = (uint32_t)__bfloat16_as_ushort(h0)
       | ((uint32_t)__bfloat16_as_ushort(h1) << 16);
    lo = (uint32_t)__bfloat16_as_ushort(l0)
       | ((uint32_t)__bfloat16_as_ushort(l1) << 16);
}

// ---------------------------------------------------------------------------
// Fused kernel: one block per graph, 512 threads, 2 CTAs/SM, HMMA stage A.
// ---------------------------------------------------------------------------
__global__ __launch_bounds__(512, 2) void ciflow_fused(
    const float* __restrict__ H,
    const int*   __restrict__ targets,
    const float* __restrict__ w1,  const float* __restrict__ b1,
    const float* __restrict__ w2,  const float* __restrict__ b2,
    const float* __restrict__ wf,  const float* __restrict__ bf,
    const float* __restrict__ p1,  const float* __restrict__ pb1,
    const float* __restrict__ p2,  const float* __restrict__ pb2,
    const float* __restrict__ ci,  const float* __restrict__ cia,
    float* __restrict__ out)
{
    extern __shared__ char smc[];
    const uint32_t sb = smem_u32(smc);

    float* Ss  = (float*)(smc + SS_B);
    float* b1s = (float*)(smc + B1S_B);
    float* W2p = (float*)(smc + W2P_B);
    float* Zrd = (float*)(smc + ZRED_B);

    const int g    = blockIdx.x;
    const int tid  = threadIdx.x;
    const int lane = tid & 31;
    const int wid  = tid >> 5;

    // ---- convert phase: f32 -> bf16 hi/lo into swizzled smem (f4/u64) ------
    const float*  Hg  = H + (size_t)g * NPG * D;
    const float4* Hg4 = (const float4*)Hg;
    for (int i = tid; i < NPG * 32; i += 512) {            // 4000 float4
        int m = i >> 5, q = i & 31;
        float4 v = Hg4[i];
        uint32_t hi0, lo0, hi1, lo1;
        bf16_split2(v.x, v.y, hi0, lo0);
        bf16_split2(v.z, v.w, hi1, lo1);
        uint32_t o = sw_off(m, 2 * q);                     // p even: p,p+1 contiguous
        *(uint2*)(smc + HHI_B + o) = make_uint2(hi0, hi1);
        *(uint2*)(smc + HLO_B + o) = make_uint2(lo0, lo1);
    }
    for (int i = tid; i < 3 * 32; i += 512) {              // zero rows 125..127
        int m = NPG + (i >> 5), q = i & 31;
        uint32_t o = sw_off(m, 2 * q);
        *(uint2*)(smc + HHI_B + o) = make_uint2(0u, 0u);
        *(uint2*)(smc + HLO_B + o) = make_uint2(0u, 0u);
    }
    for (int i = tid; i < 72 * 64; i += 512) {             // W1^T (n-major)
        int p = i / 72, n = i - p * 72;
        float x0 = (n < SH) ? w1[(2 * p)     * SH + n] : 0.0f;
        float x1 = (n < SH) ? w1[(2 * p + 1) * SH + n] : 0.0f;
        uint32_t hi, lo;
        bf16_split2(x0, x1, hi, lo);
        uint32_t o = sw_off(n, p);
        *(uint32_t*)(smc + WHI_B + o) = hi;
        *(uint32_t*)(smc + WLO_B + o) = lo;
    }
    if (tid < 72) b1s[tid] = (tid < SH) ? b1[tid] : 0.0f;
    for (int i = tid; i < 72 * 12; i += 512) {             // W2 padded [72][12]
        int r = i / 12, c = i - r * 12;
        W2p[i] = (r < SH && c < NC) ? w2[r * NC + c] : 0.0f;
    }
    __syncthreads();

    // ---- stage A via mma.sync: A = H @ W1t^T, 3-term bf16 compensation -----
    const int mtile = wid >> 1;
    const int half  = wid & 1;
    const int tA = lane >> 3, rA = lane & 7;
    const int mRow = mtile * 16 + ((tA & 1) << 3) + rA;
    const uint32_t aBase = sb + HHI_B + (uint32_t)mRow * 256u;
    const int aSw = mRow & 7, aCo = tA >> 1;
    const int nR4 = ((tA >> 1) << 3) + rA;
    const uint32_t b4Base = sb + WHI_B + (uint32_t)nR4 * 256u;
    const int b4Sw = rA, b4Co = tA & 1;
    const int t2 = (lane >> 3) & 1;
    const uint32_t b2Base = sb + WHI_B + (uint32_t)rA * 256u;
    const int b2Co = t2;

    float acc[5][4];
#pragma unroll
    for (int t = 0; t < 5; ++t)
#pragma unroll
        for (int c = 0; c < 4; ++c) acc[t][c] = 0.0f;

#pragma unroll 2
    for (int s = 0; s < 8; ++s) {
        const int c2 = 2 * s;
        uint32_t ah0, ah1, ah2, ah3, al0, al1, al2, al3;
        uint32_t aAddr = aBase + (uint32_t)(((c2 + aCo) ^ aSw) << 4);
        ldsm4(aAddr,         ah0, ah1, ah2, ah3);
        ldsm4(aAddr + 32768, al0, al1, al2, al3);

        if (half == 0) {
            uint32_t bh0, bh1, bh2, bh3, bl0, bl1, bl2, bl3;
            uint32_t bA = b4Base + (uint32_t)(((c2 + b4Co) ^ b4Sw) << 4);
            ldsm4(bA,         bh0, bh1, bh2, bh3);          // tiles 0,1
            ldsm4(bA + 18432, bl0, bl1, bl2, bl3);
            MMA(acc[0], ah0, ah1, ah2, ah3, bh0, bh1);
            MMA(acc[0], ah0, ah1, ah2, ah3, bl0, bl1);
            MMA(acc[0], al0, al1, al2, al3, bh0, bh1);
            MMA(acc[1], ah0, ah1, ah2, ah3, bh2, bh3);
            MMA(acc[1], ah0, ah1, ah2, ah3, bl2, bl3);
            MMA(acc[1], al0, al1, al2, al3, bh2, bh3);
            bA += 2u * 2048u;                               // tiles 2,3
            ldsm4(bA,         bh0, bh1, bh2, bh3);
            ldsm4(bA + 18432, bl0, bl1, bl2, bl3);
            MMA(acc[2], ah0, ah1, ah2, ah3, bh0, bh1);
            MMA(acc[2], ah0, ah1, ah2, ah3, bl0, bl1);
            MMA(acc[2], al0, al1, al2, al3, bh0, bh1);
            MMA(acc[3], ah0, ah1, ah2, ah3, bh2, bh3);
            MMA(acc[3], ah0, ah1, ah2, ah3, bl2, bl3);
            MMA(acc[3], al0, al1, al2, al3, bh2, bh3);
            uint32_t bB = b2Base + 4u * 2048u
                        + (uint32_t)(((c2 + b2Co) ^ rA) << 4);   // tile 4
            ldsm2(bB,         bh0, bh1);
            ldsm2(bB + 18432, bl0, bl1);
            MMA(acc[4], ah0, ah1, ah2, ah3, bh0, bh1);
            MMA(acc[4], ah0, ah1, ah2, ah3, bl0, bl1);
            MMA(acc[4], al0, al1, al2, al3, bh0, bh1);
        } else {
            uint32_t bh0, bh1, bh2, bh3, bl0, bl1, bl2, bl3;
            uint32_t bA = b4Base + 5u * 2048u
                        + (uint32_t)(((c2 + b4Co) ^ b4Sw) << 4); // tiles 5,6
            ldsm4(bA,         bh0, bh1, bh2, bh3);
            ldsm4(bA + 18432, bl0, bl1, bl2, bl3);
            MMA(acc[0], ah0, ah1, ah2, ah3, bh0, bh1);
            MMA(acc[0], ah0, ah1, ah2, ah3, bl0, bl1);
            MMA(acc[0], al0, al1, al2, al3, bh0, bh1);
            MMA(acc[1], ah0, ah1, ah2, ah3, bh2, bh3);
            MMA(acc[1], ah0, ah1, ah2, ah3, bl2, bl3);
            MMA(acc[1], al0, al1, al2, al3, bh2, bh3);
            bA += 2u * 2048u;                                // tiles 7,8
            ldsm4(bA,         bh0, bh1, bh2, bh3);
            ldsm4(bA + 18432, bl0, bl1, bl2, bl3);
            MMA(acc[2], ah0, ah1, ah2, ah3, bh0, bh1);
            MMA(acc[2], ah0, ah1, ah2, ah3, bl0, bl1);
            MMA(acc[2], al0, al1, al2, al3, bh0, bh1);
            MMA(acc[3], ah0, ah1, ah2, ah3, bh2, bh3);
            MMA(acc[3], ah0, ah1, ah2, ah3, bl2, bl3);
            MMA(acc[3], al0, al1, al2, al3, bh2, bh3);
        }
    }

    // ---- register epilogue: relu + b1, partial Z = A @ W2 -------------------
    const int nOff = 2 * (lane & 3);
    const int r0   = mtile * 16 + (lane >> 2);
    const int ntB  = half ? 5 : 0;
    const int ntC  = half ? 4 : 5;
    float z0[10], z1[10];
#pragma unroll
    for (int c = 0; c < 10; ++c) { z0[c] = 0.f; z1[c] = 0.f; }
#pragma unroll
    for (int ti = 0; ti < 5; ++ti) {
        if (ti < ntC) {
            int n = (ntB + ti) * 8 + nOff;
            float a00 = fmaxf(acc[ti][0] + b1s[n],     0.0f);
            float a01 = fmaxf(acc[ti][1] + b1s[n + 1], 0.0f);
            float a10 = fmaxf(acc[ti][2] + b1s[n],     0.0f);
            float a11 = fmaxf(acc[ti][3] + b1s[n + 1], 0.0f);
            const float* w2r0 = W2p + n * 12;
            const float* w2r1 = w2r0 + 12;
#pragma unroll
            for (int c = 0; c < 10; ++c) {
                float wa = w2r0[c], wb = w2r1[c];
                z0[c] = fmaf(a00, wa, fmaf(a01, wb, z0[c]));
                z1[c] = fmaf(a10, wa, fmaf(a11, wb, z1[c]));
            }
        }
    }
#pragma unroll
    for (int off = 1; off <= 2; off <<= 1) {
#pragma unroll
        for (int c = 0; c < 10; ++c) {
            z0[c] += __shfl_xor_sync(0xffffffffu, z0[c], off);
            z1[c] += __shfl_xor_sync(0xffffffffu, z1[c], off);
        }
    }
    __syncthreads();           // all ldmatrix reads of W region done
    if ((lane & 3) == 0) {
#pragma unroll
        for (int c = 0; c < 10; ++c) {
            Zrd[(half * 128 + r0) * 11 + c]     = z0[c];
            Zrd[(half * 128 + r0 + 8) * 11 + c] = z1[c];
        }
    }
    __syncthreads();

    // ---- Z combine + softmax -> S (threads 0..127); others prefetch p1/p2 --
    float* p1s = (float*)(smc + P1S_B);
    float* p2s = (float*)(smc + P2S_B);
    if (tid < 128) {
        int m = tid;
        float z[10];
#pragma unroll
        for (int c = 0; c < 10; ++c)
            z[c] = Zrd[m * 11 + c] + Zrd[(128 + m) * 11 + c] + __ldg(&b2[c]);
        if (m < NPG) {
            float mx = z[0];
#pragma unroll
            for (int c = 1; c < 10; ++c) mx = fmaxf(mx, z[c]);
            float ssum = 0.0f;
#pragma unroll
            for (int c = 0; c < 10; ++c) { z[c] = expf(z[c] - mx); ssum += z[c]; }
            float inv = 1.0f / ssum;
            float* gout = out + S_OFF + ((size_t)g * NPG + m) * NC;
#pragma unroll
            for (int c = 0; c < 10; ++c) {
                float s = z[c] * inv;
                Ss[m * NC + c] = s;
                gout[c] = s;
            }
        }
    } else {
        int t = tid - 128;
        for (int i = t; i < 1024; i += 384) p1s[i] = __ldg(&p1[i]);
        if (t < 128) p2s[t] = __ldg(&p2[t]);
    }
    __syncthreads();

    // ---- stage E: E[c][d] = sum_m S[m][c] H[m][d]; H = hi+lo from smem ------
    float* Es = (float*)(smc + ES_B);
    {
        const int d   = tid & 127;
        const int cg  = tid >> 7;
        const int c0  = (cg < 2) ? 3 * cg : 6 + 2 * (cg - 2);
        const int cnt = (cg < 2) ? 3 : 2;
        const int p   = d >> 1;
        const int sh  = (d & 1) << 4;
        const uint32_t colOff = (uint32_t)((p & 3) << 2);
        const int chunk = p >> 2;
        float e[3] = {0.f, 0.f, 0.f};
#pragma unroll 5
        for (int m = 0; m < NPG; ++m) {
            uint32_t o = (uint32_t)m * 256u
                       + (uint32_t)((chunk ^ (m & 7)) << 4) + colOff;
            uint32_t uh = *(const uint32_t*)(smc + HHI_B + o);
            uint32_t ul = *(const uint32_t*)(smc + HLO_B + o);
            float h = __uint_as_float(((uh >> sh) & 0xffffu) << 16)
                    + __uint_as_float(((ul >> sh) & 0xffffu) << 16);
#pragma unroll
            for (int j = 0; j < 3; ++j)
                if (j < cnt) e[j] = fmaf(Ss[m * NC + c0 + j], h, e[j]);
        }
        float* Eout = out + E_OFF + (size_t)g * (NC * D);
#pragma unroll
        for (int j = 0; j < 3; ++j)
            if (j < cnt) {
                Eout[(c0 + j) * D + d] = e[j];
                Es[(c0 + j) * D + d]   = e[j];
            }
    }
    __syncthreads();

    // ======================= fused downstream ================================
    float* ts    = (float*)(smc + TS_B);
    float* qraw  = (float*)(smc + QR_B);
    float* fms   = (float*)(smc + FMS_B);
    float* red   = (float*)(smc + RED_B);
    float* sc    = (float*)(smc + SC_B);
    float* corrs = (float*)(smc + CORR_B);
    float* cmask = (float*)(smc + CM_B);

    // epoch 1: pred1 partials
    float s0 = 0.f, s1 = 0.f;
#pragma unroll
    for (int r = 0; r < 3; ++r) {
        int i = tid + 512 * r;
        if (i < 1280) {
            float e = Es[i];
            float2 w = __ldg((const float2*)(wf + 2 * i));
            s0 = fmaf(e, w.x, s0);
            s1 = fmaf(e, w.y, s1);
        }
    }
#pragma unroll
    for (int off = 16; off; off >>= 1) {
        s0 += __shfl_down_sync(0xffffffffu, s0, off);
        s1 += __shfl_down_sync(0xffffffffu, s1, off);
    }
    if (lane == 0) { red[wid * 2] = s0; red[wid * 2 + 1] = s1; }
    __syncthreads();

    // epoch 2: sampling | correlation | Q hidden
    if (tid == 0) {
        float z0v = bf[0], z1v = bf[1];
#pragma unroll
        for (int w = 0; w < 16; ++w) { z0v += red[2 * w]; z1v += red[2 * w + 1]; }
        out[P1_OFF + g * 2 + 0] = z0v;
        out[P1_OFF + g * 2 + 1] = z1v;
        float mx = fmaxf(z0v, z1v);
        float e0 = expf(z0v - mx), e1 = expf(z1v - mx);
        float inv = 1.0f / (e0 + e1);
        float pp0 = e0 * inv, pp1 = e1 * inv;

        float u0 = jax_unit_uniform(2u * g);
        float u1 = jax_unit_uniform(2u * g + 1u);
        float l0 = logf(pp0 + 1e-12f) - logf(-logf(u0));
        float l1 = logf(pp1 + 1e-12f) - logf(-logf(u1));
        int sample = (l1 > l0) ? 1 : 0;

        out[IND_OFF + g] = (sample == targets[g]) ? 1.0f : 0.0f;
        sc[0] = pp0 + ((sample == 0) ? (1.0f - pp0) : -pp0);
        sc[1] = pp1 + ((sample == 1) ? (1.0f - pp1) : -pp1);
    }

    if (tid >= 32 && tid < 64) {
        int t = tid - 32;
        int c = t >> 4, f = t & 15;
        float a0 = __ldg(&ci[f]), a1 = __ldg(&ci[16 + f]);
        float m = fmaxf(a0, a1);
        float e0 = expf(a0 - m), e1 = expf(a1 - m);
        float colv = ((c == 0) ? e0 : e1) / (e0 + e1);
        float rm = -1e30f;
        for (int ff = 0; ff < 16; ++ff) rm = fmaxf(rm, __ldg(&cia[c * 16 + ff]));
        float rs = 0.f;
        for (int ff = 0; ff < 16; ++ff) rs += expf(__ldg(&cia[c * 16 + ff]) - rm);
        corrs[c * 16 + f] = colv * (expf(__ldg(&cia[c * 16 + f]) - rm) / rs);
    }

    if (tid >= 192) {                // Q hidden, 4-way k-split
        int t  = tid - 192;
        int u  = t >> 2, ks = t & 3;
        int c  = u >> 3, j = u & 7;
        float a = 0.0f;
        const float* ec = Es + c * 128 + 32 * ks;
        const float* pj = p1s + (32 * ks) * 8 + j;
#pragma unroll 8
        for (int k = 0; k < 32; ++k) a = fmaf(ec[k], pj[8 * k], a);
        a += __shfl_down_sync(0xffffffffu, a, 2);
        a += __shfl_down_sync(0xffffffffu, a, 1);
        if (ks == 0) ts[u] = fmaxf(a + __ldg(&pb1[j]), 0.0f);
    }
    __syncthreads();

    // epoch 3: cmask | Q output
    if (tid < 16) cmask[tid] = sc[0] * corrs[tid] + sc[1] * corrs[16 + tid];

    if (tid >= 160 && tid < 320) {
        int t = tid - 160;
        int c = t >> 4, f = t & 15;
        float a = __ldg(&pb2[f]);
#pragma unroll
        for (int j = 0; j < 8; ++j) a = fmaf(ts[c * 8 + j], p2s[j * 16 + f], a);
        qraw[t] = a;
    }
    __syncthreads();

    // epoch 4: Q softmax + feature mask
    if (tid < 160) {
        int c = tid >> 4, f = tid & 15;
        float v = qraw[tid];
        float mx = v;
#pragma unroll
        for (int off = 8; off; off >>= 1)
            mx = fmaxf(mx, __shfl_xor_sync(0xffffffffu, mx, off));
        float e = expf(v - mx);
        float ssum = e;
#pragma unroll
        for (int off = 8; off; off >>= 1)
            ssum += __shfl_xor_sync(0xffffffffu, ssum, off);
        float q = e / ssum;
        out[Q_OFF + (size_t)g * 160 + c * 16 + f] = q;
        float fm = q * cmask[f];
#pragma unroll
        for (int off = 8; off; off >>= 1)
            fm += __shfl_xor_sync(0xffffffffu, fm, off);
        if (f == 0) fms[c] = fm;
    }
    __syncthreads();

    // epoch 5: pred2
    s0 = 0.f; s1 = 0.f;
#pragma unroll
    for (int r = 0; r < 3; ++r) {
        int i = tid + 512 * r;
        if (i < 1280) {
            float e = fms[i >> 7] * Es[i];
            float2 w = __ldg((const float2*)(wf + 2 * i));
            s0 = fmaf(e, w.x, s0);
            s1 = fmaf(e, w.y, s1);
        }
    }
#pragma unroll
    for (int off = 16; off; off >>= 1) {
        s0 += __shfl_down_sync(0xffffffffu, s0, off);
        s1 += __shfl_down_sync(0xffffffffu, s1, off);
    }
    if (lane == 0) { red[wid * 2] = s0; red[wid * 2 + 1] = s1; }
    __syncthreads();
    if (tid == 0) {
        float z0v = bf[0], z1v = bf[1];
#pragma unroll
        for (int w = 0; w < 16; ++w) { z0v += red[2 * w]; z1v += red[2 * w + 1]; }
        out[P2_OFF + g * 2 + 0] = z0v;
        out[P2_OFF + g * 2 + 1] = z1v;
    }
}

// ---------------------------------------------------------------------------
extern "C" void kernel_launch(void* const* d_in, const int* in_sizes, int n_in,
                              void* d_out, int out_size)
{
    const float* H   = (const float*)d_in[0];
    const int*   tgt = (const int*)  d_in[2];
    const float* w1  = (const float*)d_in[3];
    const float* b1  = (const float*)d_in[4];
    const float* w2  = (const float*)d_in[5];
    const float* b2  = (const float*)d_in[6];
    const float* wf  = (const float*)d_in[7];
    const float* bf  = (const float*)d_in[8];
    const float* p1  = (const float*)d_in[9];
    const float* pb1 = (const float*)d_in[10];
    const float* p2  = (const float*)d_in[11];
    const float* pb2 = (const float*)d_in[12];
    const float* ci  = (const float*)d_in[13];
    const float* cia = (const float*)d_in[14];
    float* out = (float*)d_out;

    static bool attr_set = false;
    if (!attr_set) {
        cudaFuncSetAttribute(ciflow_fused,
                             cudaFuncAttributeMaxDynamicSharedMemorySize, SMEM_TOTAL);
        attr_set = true;
    }

    ciflow_fused<<<NGRAPH, 512, SMEM_TOTAL>>>(H, tgt, w1, b1, w2, b2, wf, bf,
                                              p1, pb1, p2, pb2, ci, cia, out);
}

// round 10
// speedup vs baseline: 2.5032x; 1.3241x over previous
#include <cuda_runtime.h>
#include <cuda_bf16.h>
#include <cstdint>

// Problem constants
#define NGRAPH 512
#define NPG    125
#define D      128
#define SH     69
#define NC     10

// d_out float offsets
#define P1_OFF  0
#define P2_OFF  1024
#define IND_OFF 2048
#define S_OFF   2560
#define E_OFF   642560
#define Q_OFF   1297920

// ---- smem layout (bytes) ---------------------------------------------------
#define HHI_B   0          // H hi  [128][128] bf16, XOR-swizzled (32768) - live thru E
#define HLO_B   32768      // H lo  (32768) - live thru E
#define WHI_B   65536      // W1^T hi (18432); aliased after stage A
#define WLO_B   83968      // W1^T lo (18432); aliased after stage A
// aliases into the dead W region
#define ZRED_B  65536      // Zred [2][128][11] f32 = 11264
#define STHI_B  76800      // S^T hi [16][128] bf16 swizzled (4096)
#define STLO_B  80896      // S^T lo (4096)
#define ES_B    84992      // Es 1280 f (5120)
#define P1S_B   90112      // 1024 f
#define P2S_B   94208      // 128 f
#define TS_B    94720      // 80 f
#define QR_B    95040      // 160 f
// persistent
#define B1S_B   107400     // 72 f
#define W2P_B   107696     // W2 padded [72][12] f32 (3456)
#define RED_B   111152     // 32 f
#define SC_B    111280     // 2 f
#define CORR_B  111288     // 32 f
#define CM_B    111416     // 16 f
#define FMS_B   111480     // 16 f
#define SMEM_TOTAL 111552  // ~108.9 KB -> 2 CTAs/SM

// ---------------------------------------------------------------------------
__device__ __forceinline__ uint32_t smem_u32(const void* p) {
    uint32_t a;
    asm("{ .reg .u64 t; cvta.to.shared.u64 t, %1; cvt.u32.u64 %0, t; }"
        : "=r"(a) : "l"(p));
    return a;
}
__device__ __forceinline__ void ldsm4(uint32_t a, uint32_t& r0, uint32_t& r1,
                                      uint32_t& r2, uint32_t& r3) {
    asm volatile("ldmatrix.sync.aligned.m8n8.x4.shared.b16 {%0,%1,%2,%3}, [%4];"
                 : "=r"(r0), "=r"(r1), "=r"(r2), "=r"(r3) : "r"(a));
}
__device__ __forceinline__ void ldsm2(uint32_t a, uint32_t& r0, uint32_t& r1) {
    asm volatile("ldmatrix.sync.aligned.m8n8.x2.shared.b16 {%0,%1}, [%2];"
                 : "=r"(r0), "=r"(r1) : "r"(a));
}
__device__ __forceinline__ void ldsm2t(uint32_t a, uint32_t& r0, uint32_t& r1) {
    asm volatile("ldmatrix.sync.aligned.m8n8.x2.trans.shared.b16 {%0,%1}, [%2];"
                 : "=r"(r0), "=r"(r1) : "r"(a));
}
#define MMA(ac, a0, a1, a2, a3, b0, b1) \
    asm volatile("mma.sync.aligned.m16n8k16.row.col.f32.bf16.bf16.f32 " \
                 "{%0,%1,%2,%3}, {%4,%5,%6,%7}, {%8,%9}, {%0,%1,%2,%3};" \
                 : "+f"((ac)[0]), "+f"((ac)[1]), "+f"((ac)[2]), "+f"((ac)[3]) \
                 : "r"(a0), "r"(a1), "r"(a2), "r"(a3), "r"(b0), "r"(b1))

// element (row, bf16-pair p) -> swizzled byte offset (row stride 256B)
__device__ __forceinline__ uint32_t sw_off(int row, int p) {
    return (uint32_t)row * 256u + (uint32_t)(((p >> 2) ^ (row & 7)) << 4)
         + (uint32_t)((p & 3) << 2);
}

// ---------------------------------------------------------------------------
// Threefry-2x32 (JAX partitionable) — bit-exact since R1
// ---------------------------------------------------------------------------
__device__ __forceinline__ void threefry2x32(uint32_t k0, uint32_t k1,
                                             uint32_t c0, uint32_t c1,
                                             uint32_t& y0, uint32_t& y1)
{
    uint32_t ks2 = k0 ^ k1 ^ 0x1BD11BDAu;
    uint32_t x0 = c0 + k0, x1 = c1 + k1;
#define TF_RND(r) { x0 += x1; x1 = (x1 << (r)) | (x1 >> (32 - (r))); x1 ^= x0; }
    TF_RND(13) TF_RND(15) TF_RND(26) TF_RND(6)  x0 += k1;  x1 += ks2 + 1u;
    TF_RND(17) TF_RND(29) TF_RND(16) TF_RND(24) x0 += ks2; x1 += k0  + 2u;
    TF_RND(13) TF_RND(15) TF_RND(26) TF_RND(6)  x0 += k0;  x1 += k1  + 3u;
    TF_RND(17) TF_RND(29) TF_RND(16) TF_RND(24) x0 += k1;  x1 += ks2 + 4u;
    TF_RND(13) TF_RND(15) TF_RND(26) TF_RND(6)  x0 += ks2; x1 += k0  + 5u;
#undef TF_RND
    y0 = x0; y1 = x1;
}
__device__ __forceinline__ float jax_unit_uniform(uint32_t f)
{
    uint32_t y0, y1;
    threefry2x32(0u, 42u, 0u, f, y0, y1);
    uint32_t bits = y0 ^ y1;
    float v = __uint_as_float((bits >> 9) | 0x3f800000u) - 1.0f;
    return (v == 0.0f) ? 1.17549435e-38f : v;
}

// split f32 -> (hi, lo) bf16 pair packed as u32 x2
__device__ __forceinline__ void bf16_split2(float x0, float x1,
                                            uint32_t& hi, uint32_t& lo)
{
    __nv_bfloat16 h0 = __float2bfloat16(x0);
    __nv_bfloat16 h1 = __float2bfloat16(x1);
    __nv_bfloat16 l0 = __float2bfloat16(x0 - __bfloat162float(h0));
    __nv_bfloat16 l1 = __float2bfloat16(x1 - __bfloat162float(h1));
    hi = (uint32_t)__bfloat16_as_ushort(h0)
       | ((uint32_t)__bfloat16_as_ushort(h1) << 16);
    lo = (uint32_t)__bfloat16_as_ushort(l0)
       | ((uint32_t)__bfloat16_as_ushort(l1) << 16);
}

// ---------------------------------------------------------------------------
// Fused kernel: one block per graph, 512 threads, 2 CTAs/SM, HMMA A + E.
// ---------------------------------------------------------------------------
__global__ __launch_bounds__(512, 2) void ciflow_fused(
    const float* __restrict__ H,
    const int*   __restrict__ targets,
    const float* __restrict__ w1,  const float* __restrict__ b1,
    const float* __restrict__ w2,  const float* __restrict__ b2,
    const float* __restrict__ wf,  const float* __restrict__ bf,
    const float* __restrict__ p1,  const float* __restrict__ pb1,
    const float* __restrict__ p2,  const float* __restrict__ pb2,
    const float* __restrict__ ci,  const float* __restrict__ cia,
    float* __restrict__ out)
{
    extern __shared__ char smc[];
    const uint32_t sb = smem_u32(smc);

    float* b1s = (float*)(smc + B1S_B);
    float* W2p = (float*)(smc + W2P_B);
    float* Zrd = (float*)(smc + ZRED_B);

    const int g    = blockIdx.x;
    const int tid  = threadIdx.x;
    const int lane = tid & 31;
    const int wid  = tid >> 5;

    // ---- convert phase: f32 -> bf16 hi/lo into swizzled smem ----------------
    const float*  Hg  = H + (size_t)g * NPG * D;
    const float4* Hg4 = (const float4*)Hg;
    for (int i = tid; i < NPG * 32; i += 512) {            // 4000 float4
        int m = i >> 5, q = i & 31;
        float4 v = Hg4[i];
        uint32_t hi0, lo0, hi1, lo1;
        bf16_split2(v.x, v.y, hi0, lo0);
        bf16_split2(v.z, v.w, hi1, lo1);
        uint32_t o = sw_off(m, 2 * q);
        *(uint2*)(smc + HHI_B + o) = make_uint2(hi0, hi1);
        *(uint2*)(smc + HLO_B + o) = make_uint2(lo0, lo1);
    }
    for (int i = tid; i < 3 * 32; i += 512) {              // zero rows 125..127
        int m = NPG + (i >> 5), q = i & 31;
        uint32_t o = sw_off(m, 2 * q);
        *(uint2*)(smc + HHI_B + o) = make_uint2(0u, 0u);
        *(uint2*)(smc + HLO_B + o) = make_uint2(0u, 0u);
    }
    for (int i = tid; i < 72 * 64; i += 512) {             // W1^T (n-major)
        int p = i / 72, n = i - p * 72;
        float x0 = (n < SH) ? w1[(2 * p)     * SH + n] : 0.0f;
        float x1 = (n < SH) ? w1[(2 * p + 1) * SH + n] : 0.0f;
        uint32_t hi, lo;
        bf16_split2(x0, x1, hi, lo);
        uint32_t o = sw_off(n, p);
        *(uint32_t*)(smc + WHI_B + o) = hi;
        *(uint32_t*)(smc + WLO_B + o) = lo;
    }
    if (tid < 72) b1s[tid] = (tid < SH) ? b1[tid] : 0.0f;
    for (int i = tid; i < 72 * 12; i += 512) {             // W2 padded [72][12]
        int r = i / 12, c = i - r * 12;
        W2p[i] = (r < SH && c < NC) ? w2[r * NC + c] : 0.0f;
    }
    __syncthreads();

    // ---- stage A via mma.sync: A = H @ W1t^T, 3-term bf16 compensation -----
    const int mtile = wid >> 1;
    const int half  = wid & 1;
    const int tA = lane >> 3, rA = lane & 7;
    const int mRow = mtile * 16 + ((tA & 1) << 3) + rA;
    const uint32_t aBase = sb + HHI_B + (uint32_t)mRow * 256u;
    const int aSw = mRow & 7, aCo = tA >> 1;
    const int nR4 = ((tA >> 1) << 3) + rA;
    const uint32_t b4Base = sb + WHI_B + (uint32_t)nR4 * 256u;
    const int b4Sw = rA, b4Co = tA & 1;
    const int t2 = (lane >> 3) & 1;
    const uint32_t b2Base = sb + WHI_B + (uint32_t)rA * 256u;
    const int b2Co = t2;

    float acc[5][4];
#pragma unroll
    for (int t = 0; t < 5; ++t)
#pragma unroll
        for (int c = 0; c < 4; ++c) acc[t][c] = 0.0f;

#pragma unroll 2
    for (int s = 0; s < 8; ++s) {
        const int c2 = 2 * s;
        uint32_t ah0, ah1, ah2, ah3, al0, al1, al2, al3;
        uint32_t aAddr = aBase + (uint32_t)(((c2 + aCo) ^ aSw) << 4);
        ldsm4(aAddr,         ah0, ah1, ah2, ah3);
        ldsm4(aAddr + 32768, al0, al1, al2, al3);

        if (half == 0) {
            uint32_t bh0, bh1, bh2, bh3, bl0, bl1, bl2, bl3;
            uint32_t bA = b4Base + (uint32_t)(((c2 + b4Co) ^ b4Sw) << 4);
            ldsm4(bA,         bh0, bh1, bh2, bh3);          // tiles 0,1
            ldsm4(bA + 18432, bl0, bl1, bl2, bl3);
            MMA(acc[0], ah0, ah1, ah2, ah3, bh0, bh1);
            MMA(acc[0], ah0, ah1, ah2, ah3, bl0, bl1);
            MMA(acc[0], al0, al1, al2, al3, bh0, bh1);
            MMA(acc[1], ah0, ah1, ah2, ah3, bh2, bh3);
            MMA(acc[1], ah0, ah1, ah2, ah3, bl2, bl3);
            MMA(acc[1], al0, al1, al2, al3, bh2, bh3);
            bA += 2u * 2048u;                               // tiles 2,3
            ldsm4(bA,         bh0, bh1, bh2, bh3);
            ldsm4(bA + 18432, bl0, bl1, bl2, bl3);
            MMA(acc[2], ah0, ah1, ah2, ah3, bh0, bh1);
            MMA(acc[2], ah0, ah1, ah2, ah3, bl0, bl1);
            MMA(acc[2], al0, al1, al2, al3, bh0, bh1);
            MMA(acc[3], ah0, ah1, ah2, ah3, bh2, bh3);
            MMA(acc[3], ah0, ah1, ah2, ah3, bl2, bl3);
            MMA(acc[3], al0, al1, al2, al3, bh2, bh3);
            uint32_t bB = b2Base + 4u * 2048u
                        + (uint32_t)(((c2 + b2Co) ^ rA) << 4);   // tile 4
            ldsm2(bB,         bh0, bh1);
            ldsm2(bB + 18432, bl0, bl1);
            MMA(acc[4], ah0, ah1, ah2, ah3, bh0, bh1);
            MMA(acc[4], ah0, ah1, ah2, ah3, bl0, bl1);
            MMA(acc[4], al0, al1, al2, al3, bh0, bh1);
        } else {
            uint32_t bh0, bh1, bh2, bh3, bl0, bl1, bl2, bl3;
            uint32_t bA = b4Base + 5u * 2048u
                        + (uint32_t)(((c2 + b4Co) ^ b4Sw) << 4); // tiles 5,6
            ldsm4(bA,         bh0, bh1, bh2, bh3);
            ldsm4(bA + 18432, bl0, bl1, bl2, bl3);
            MMA(acc[0], ah0, ah1, ah2, ah3, bh0, bh1);
            MMA(acc[0], ah0, ah1, ah2, ah3, bl0, bl1);
            MMA(acc[0], al0, al1, al2, al3, bh0, bh1);
            MMA(acc[1], ah0, ah1, ah2, ah3, bh2, bh3);
            MMA(acc[1], ah0, ah1, ah2, ah3, bl2, bl3);
            MMA(acc[1], al0, al1, al2, al3, bh2, bh3);
            bA += 2u * 2048u;                                // tiles 7,8
            ldsm4(bA,         bh0, bh1, bh2, bh3);
            ldsm4(bA + 18432, bl0, bl1, bl2, bl3);
            MMA(acc[2], ah0, ah1, ah2, ah3, bh0, bh1);
            MMA(acc[2], ah0, ah1, ah2, ah3, bl0, bl1);
            MMA(acc[2], al0, al1, al2, al3, bh0, bh1);
            MMA(acc[3], ah0, ah1, ah2, ah3, bh2, bh3);
            MMA(acc[3], ah0, ah1, ah2, ah3, bl2, bl3);
            MMA(acc[3], al0, al1, al2, al3, bh2, bh3);
        }
    }

    // ---- register epilogue: relu + b1, partial Z = A @ W2 -------------------
    const int nOff = 2 * (lane & 3);
    const int r0   = mtile * 16 + (lane >> 2);
    const int ntB  = half ? 5 : 0;
    const int ntC  = half ? 4 : 5;
    float z0[10], z1[10];
#pragma unroll
    for (int c = 0; c < 10; ++c) { z0[c] = 0.f; z1[c] = 0.f; }
#pragma unroll
    for (int ti = 0; ti < 5; ++ti) {
        if (ti < ntC) {
            int n = (ntB + ti) * 8 + nOff;
            float a00 = fmaxf(acc[ti][0] + b1s[n],     0.0f);
            float a01 = fmaxf(acc[ti][1] + b1s[n + 1], 0.0f);
            float a10 = fmaxf(acc[ti][2] + b1s[n],     0.0f);
            float a11 = fmaxf(acc[ti][3] + b1s[n + 1], 0.0f);
            const float* w2r0 = W2p + n * 12;
            const float* w2r1 = w2r0 + 12;
#pragma unroll
            for (int c = 0; c < 10; ++c) {
                float wa = w2r0[c], wb = w2r1[c];
                z0[c] = fmaf(a00, wa, fmaf(a01, wb, z0[c]));
                z1[c] = fmaf(a10, wa, fmaf(a11, wb, z1[c]));
            }
        }
    }
#pragma unroll
    for (int off = 1; off <= 2; off <<= 1) {
#pragma unroll
        for (int c = 0; c < 10; ++c) {
            z0[c] += __shfl_xor_sync(0xffffffffu, z0[c], off);
            z1[c] += __shfl_xor_sync(0xffffffffu, z1[c], off);
        }
    }
    __syncthreads();           // all ldmatrix reads of W region done
    if ((lane & 3) == 0) {
#pragma unroll
        for (int c = 0; c < 10; ++c) {
            Zrd[(half * 128 + r0) * 11 + c]     = z0[c];
            Zrd[(half * 128 + r0 + 8) * 11 + c] = z1[c];
        }
    }
    __syncthreads();

    // ---- Z combine + softmax -> S gmem + S^T bf16 hi/lo; others prefetch ---
    float* p1s = (float*)(smc + P1S_B);
    float* p2s = (float*)(smc + P2S_B);
    if (tid < 128) {
        int m = tid;
        const uint32_t mChunk = (uint32_t)((m >> 3) << 4);
        const uint32_t mRem   = (uint32_t)(((m >> 1) & 3) << 2)
                              + (uint32_t)((m & 1) << 1);
        if (m < NPG) {
            float z[10];
#pragma unroll
            for (int c = 0; c < 10; ++c)
                z[c] = Zrd[m * 11 + c] + Zrd[(128 + m) * 11 + c] + __ldg(&b2[c]);
            float mx = z[0];
#pragma unroll
            for (int c = 1; c < 10; ++c) mx = fmaxf(mx, z[c]);
            float ssum = 0.0f;
#pragma unroll
            for (int c = 0; c < 10; ++c) { z[c] = expf(z[c] - mx); ssum += z[c]; }
            float inv = 1.0f / ssum;
            float* gout = out + S_OFF + ((size_t)g * NPG + m) * NC;
#pragma unroll
            for (int c = 0; c < 10; ++c) {
                float s = z[c] * inv;
                gout[c] = s;
                __nv_bfloat16 shi = __float2bfloat16(s);
                __nv_bfloat16 slo = __float2bfloat16(s - __bfloat162float(shi));
                uint32_t off = (uint32_t)c * 256u
                             + ((mChunk ^ (uint32_t)((c & 7) << 4))) + mRem;
                *(unsigned short*)(smc + STHI_B + off) = __bfloat16_as_ushort(shi);
                *(unsigned short*)(smc + STLO_B + off) = __bfloat16_as_ushort(slo);
            }
        } else {
            // m = 125..127: zero K-pad columns of S^T (all 16 rows)
#pragma unroll
            for (int c = 0; c < 16; ++c) {
                uint32_t off = (uint32_t)c * 256u
                             + ((mChunk ^ (uint32_t)((c & 7) << 4))) + mRem;
                *(unsigned short*)(smc + STHI_B + off) = 0;
                *(unsigned short*)(smc + STLO_B + off) = 0;
            }
        }
    } else {
        int t = tid - 128;
        for (int i = t; i < 1024; i += 384) p1s[i] = __ldg(&p1[i]);
        if (t < 128) p2s[t] = __ldg(&p2[t]);
    }
    __syncthreads();

    // ---- stage E via mma: E = S^T @ H; per-warp 8-column d-tile -------------
    float* Es = (float*)(smc + ES_B);
    {
        const int aRow = ((tA & 1) << 3) + rA;
        const uint32_t aHiBase = sb + STHI_B + (uint32_t)aRow * 256u;
        const int aXor = aRow & 7;
        const int bOff = lane & 15;                    // H row within k-step
        uint32_t bAddr = sb + HHI_B + (uint32_t)bOff * 256u
                       + (uint32_t)((wid ^ (bOff & 7)) << 4);

        float e[4] = {0.f, 0.f, 0.f, 0.f};
#pragma unroll
        for (int s = 0; s < 8; ++s) {
            uint32_t aAddr = aHiBase + (uint32_t)(((2 * s + aCo) ^ aXor) << 4);
            uint32_t sh0, sh1, sh2, sh3, sl0, sl1, sl2, sl3;
            ldsm4(aAddr,        sh0, sh1, sh2, sh3);
            ldsm4(aAddr + 4096, sl0, sl1, sl2, sl3);   // STLO = STHI + 4096
            uint32_t bh0, bh1, bl0, bl1;
            ldsm2t(bAddr,         bh0, bh1);
            ldsm2t(bAddr + 32768, bl0, bl1);           // HLO
            MMA(e, sh0, sh1, sh2, sh3, bh0, bh1);
            MMA(e, sh0, sh1, sh2, sh3, bl0, bl1);
            MMA(e, sl0, sl1, sl2, sl3, bh0, bh1);
            bAddr += 16u * 256u;
        }
        const int c = lane >> 2;
        const int d = 8 * wid + 2 * (lane & 3);
        float* Eout = out + E_OFF + (size_t)g * (NC * D);
        Es[c * D + d]       = e[0];
        Es[c * D + d + 1]   = e[1];
        Eout[c * D + d]     = e[0];
        Eout[c * D + d + 1] = e[1];
        if (c + 8 < NC) {
            Es[(c + 8) * D + d]       = e[2];
            Es[(c + 8) * D + d + 1]   = e[3];
            Eout[(c + 8) * D + d]     = e[2];
            Eout[(c + 8) * D + d + 1] = e[3];
        }
    }
    __syncthreads();

    // ======================= fused downstream ================================
    float* ts    = (float*)(smc + TS_B);
    float* qraw  = (float*)(smc + QR_B);
    float* fms   = (float*)(smc + FMS_B);
    float* red   = (float*)(smc + RED_B);
    float* sc    = (float*)(smc + SC_B);
    float* corrs = (float*)(smc + CORR_B);
    float* cmask = (float*)(smc + CM_B);

    // epoch 1: pred1 partials
    float s0 = 0.f, s1 = 0.f;
#pragma unroll
    for (int r = 0; r < 3; ++r) {
        int i = tid + 512 * r;
        if (i < 1280) {
            float e = Es[i];
            float2 w = __ldg((const float2*)(wf + 2 * i));
            s0 = fmaf(e, w.x, s0);
            s1 = fmaf(e, w.y, s1);
        }
    }
#pragma unroll
    for (int off = 16; off; off >>= 1) {
        s0 += __shfl_down_sync(0xffffffffu, s0, off);
        s1 += __shfl_down_sync(0xffffffffu, s1, off);
    }
    if (lane == 0) { red[wid * 2] = s0; red[wid * 2 + 1] = s1; }
    __syncthreads();

    // epoch 2: sampling | correlation | Q hidden
    if (tid == 0) {
        float z0v = bf[0], z1v = bf[1];
#pragma unroll
        for (int w = 0; w < 16; ++w) { z0v += red[2 * w]; z1v += red[2 * w + 1]; }
        out[P1_OFF + g * 2 + 0] = z0v;
        out[P1_OFF + g * 2 + 1] = z1v;
        float mx = fmaxf(z0v, z1v);
        float e0 = expf(z0v - mx), e1 = expf(z1v - mx);
        float inv = 1.0f / (e0 + e1);
        float pp0 = e0 * inv, pp1 = e1 * inv;

        float u0 = jax_unit_uniform(2u * g);
        float u1 = jax_unit_uniform(2u * g + 1u);
        float l0 = logf(pp0 + 1e-12f) - logf(-logf(u0));
        float l1 = logf(pp1 + 1e-12f) - logf(-logf(u1));
        int sample = (l1 > l0) ? 1 : 0;

        out[IND_OFF + g] = (sample == targets[g]) ? 1.0f : 0.0f;
        sc[0] = pp0 + ((sample == 0) ? (1.0f - pp0) : -pp0);
        sc[1] = pp1 + ((sample == 1) ? (1.0f - pp1) : -pp1);
    }

    if (tid >= 32 && tid < 64) {
        int t = tid - 32;
        int c = t >> 4, f = t & 15;
        float a0 = __ldg(&ci[f]), a1 = __ldg(&ci[16 + f]);
        float m = fmaxf(a0, a1);
        float e0 = expf(a0 - m), e1 = expf(a1 - m);
        float colv = ((c == 0) ? e0 : e1) / (e0 + e1);
        float rm = -1e30f;
        for (int ff = 0; ff < 16; ++ff) rm = fmaxf(rm, __ldg(&cia[c * 16 + ff]));
        float rs = 0.f;
        for (int ff = 0; ff < 16; ++ff) rs += expf(__ldg(&cia[c * 16 + ff]) - rm);
        corrs[c * 16 + f] = colv * (expf(__ldg(&cia[c * 16 + f]) - rm) / rs);
    }

    if (tid >= 192) {                // Q hidden, 4-way k-split
        int t  = tid - 192;
        int u  = t >> 2, ks = t & 3;
        int c  = u >> 3, j = u & 7;
        float a = 0.0f;
        const float* ec = Es + c * 128 + 32 * ks;
        const float* pj = p1s + (32 * ks) * 8 + j;
#pragma unroll 8
        for (int k = 0; k < 32; ++k) a = fmaf(ec[k], pj[8 * k], a);
        a += __shfl_down_sync(0xffffffffu, a, 2);
        a += __shfl_down_sync(0xffffffffu, a, 1);
        if (ks == 0) ts[u] = fmaxf(a + __ldg(&pb1[j]), 0.0f);
    }
    __syncthreads();

    // epoch 3: cmask | Q output
    if (tid < 16) cmask[tid] = sc[0] * corrs[tid] + sc[1] * corrs[16 + tid];

    if (tid >= 160 && tid < 320) {
        int t = tid - 160;
        int c = t >> 4, f = t & 15;
        float a = __ldg(&pb2[f]);
#pragma unroll
        for (int j = 0; j < 8; ++j) a = fmaf(ts[c * 8 + j], p2s[j * 16 + f], a);
        qraw[t] = a;
    }
    __syncthreads();

    // epoch 4: Q softmax + feature mask
    if (tid < 160) {
        int c = tid >> 4, f = tid & 15;
        float v = qraw[tid];
        float mx = v;
#pragma unroll
        for (int off = 8; off; off >>= 1)
            mx = fmaxf(mx, __shfl_xor_sync(0xffffffffu, mx, off));
        float e = expf(v - mx);
        float ssum = e;
#pragma unroll
        for (int off = 8; off; off >>= 1)
            ssum += __shfl_xor_sync(0xffffffffu, ssum, off);
        float q = e / ssum;
        out[Q_OFF + (size_t)g * 160 + c * 16 + f] = q;
        float fm = q * cmask[f];
#pragma unroll
        for (int off = 8; off; off >>= 1)
            fm += __shfl_xor_sync(0xffffffffu, fm, off);
        if (f == 0) fms[c] = fm;
    }
    __syncthreads();

    // epoch 5: pred2
    s0 = 0.f; s1 = 0.f;
#pragma unroll
    for (int r = 0; r < 3; ++r) {
        int i = tid + 512 * r;
        if (i < 1280) {
            float e = fms[i >> 7] * Es[i];
            float2 w = __ldg((const float2*)(wf + 2 * i));
            s0 = fmaf(e, w.x, s0);
            s1 = fmaf(e, w.y, s1);
        }
    }
#pragma unroll
    for (int off = 16; off; off >>= 1) {
        s0 += __shfl_down_sync(0xffffffffu, s0, off);
        s1 += __shfl_down_sync(0xffffffffu, s1, off);
    }
    if (lane == 0) { red[wid * 2] = s0; red[wid * 2 + 1] = s1; }
    __syncthreads();
    if (tid == 0) {
        float z0v = bf[0], z1v = bf[1];
#pragma unroll
        for (int w = 0; w < 16; ++w) { z0v += red[2 * w]; z1v += red[2 * w + 1]; }
        out[P2_OFF + g * 2 + 0] = z0v;
        out[P2_OFF + g * 2 + 1] = z1v;
    }
}

// ---------------------------------------------------------------------------
extern "C" void kernel_launch(void* const* d_in, const int* in_sizes, int n_in,
                              void* d_out, int out_size)
{
    const float* H   = (const float*)d_in[0];
    const int*   tgt = (const int*)  d_in[2];
    const float* w1  = (const float*)d_in[3];
    const float* b1  = (const float*)d_in[4];
    const float* w2  = (const float*)d_in[5];
    const float* b2  = (const float*)d_in[6];
    const float* wf  = (const float*)d_in[7];
    const float* bf  = (const float*)d_in[8];
    const float* p1  = (const float*)d_in[9];
    const float* pb1 = (const float*)d_in[10];
    const float* p2  = (const float*)d_in[11];
    const float* pb2 = (const float*)d_in[12];
    const float* ci  = (const float*)d_in[13];
    const float* cia = (const float*)d_in[14];
    float* out = (float*)d_out;

    static bool attr_set = false;
    if (!attr_set) {
        cudaFuncSetAttribute(ciflow_fused,
                             cudaFuncAttributeMaxDynamicSharedMemorySize, SMEM_TOTAL);
        attr_set = true;
    }

    ciflow_fused<<<NGRAPH, 512, SMEM_TOTAL>>>(H, tgt, w1, b1, w2, b2, wf, bf,
                                              p1, pb1, p2, pb2, ci, cia, out);
}

// round 11
// speedup vs baseline: 2.8733x; 1.1478x over previous
#include <cuda_runtime.h>
#include <cuda_bf16.h>
#include <cstdint>

// Problem constants
#define NGRAPH 512
#define NPG    125
#define D      128
#define SH     69
#define NC     10

// d_out float offsets
#define P1_OFF  0
#define P2_OFF  1024
#define IND_OFF 2048
#define S_OFF   2560
#define E_OFF   642560
#define Q_OFF   1297920

// ---- smem layout (bytes) ---------------------------------------------------
#define HHI_B   0          // H hi  [128][128] bf16, XOR-swizzled (32768) - live thru E
#define HLO_B   32768      // H lo  (32768) - live thru E
#define WHI_B   65536      // W1^T hi (18432); aliased after stage A
#define WLO_B   83968      // W1^T lo (18432); aliased after stage A
// aliases into the dead W region
#define ZRED_B  65536      // Zred [2][128][11] f32 = 11264
#define STHI_B  76800      // S^T hi [16][128] bf16 swizzled (4096)
#define STLO_B  80896      // S^T lo (4096)
#define ES_B    84992      // Es 1280 f (5120)
#define P1S_B   90112      // 1024 f
#define P2S_B   94208      // 128 f
#define TS_B    94720      // 80 f
#define QR_B    95040      // 160 f
// persistent (16B-aligned where float4-copied)
#define B1S_B   107392     // 72 f (288)
#define W2P_B   107680     // W2 padded [72][12] f32 (3456)
#define RED_B   111136     // 32 f
#define SC_B    111264     // 2 f
#define CORR_B  111272     // 32 f
#define CM_B    111400     // 16 f
#define FMS_B   111464     // 16 f
#define SMEM_TOTAL 111552  // ~108.9 KB -> 2 CTAs/SM

// ---- precomputed weight images (written by ciflow_prep) --------------------
__device__ __align__(16) uint32_t gW1HI[4608];   // 18432 B swizzled image
__device__ __align__(16) uint32_t gW1LO[4608];
__device__ __align__(16) float    gW2P[864];     // [72][12]
__device__ __align__(16) float    gB1[72];

// ---------------------------------------------------------------------------
__device__ __forceinline__ uint32_t smem_u32(const void* p) {
    uint32_t a;
    asm("{ .reg .u64 t; cvta.to.shared.u64 t, %1; cvt.u32.u64 %0, t; }"
        : "=r"(a) : "l"(p));
    return a;
}
__device__ __forceinline__ void ldsm4(uint32_t a, uint32_t& r0, uint32_t& r1,
                                      uint32_t& r2, uint32_t& r3) {
    asm volatile("ldmatrix.sync.aligned.m8n8.x4.shared.b16 {%0,%1,%2,%3}, [%4];"
                 : "=r"(r0), "=r"(r1), "=r"(r2), "=r"(r3) : "r"(a));
}
__device__ __forceinline__ void ldsm2(uint32_t a, uint32_t& r0, uint32_t& r1) {
    asm volatile("ldmatrix.sync.aligned.m8n8.x2.shared.b16 {%0,%1}, [%2];"
                 : "=r"(r0), "=r"(r1) : "r"(a));
}
__device__ __forceinline__ void ldsm2t(uint32_t a, uint32_t& r0, uint32_t& r1) {
    asm volatile("ldmatrix.sync.aligned.m8n8.x2.trans.shared.b16 {%0,%1}, [%2];"
                 : "=r"(r0), "=r"(r1) : "r"(a));
}
#define MMA(ac, a0, a1, a2, a3, b0, b1) \
    asm volatile("mma.sync.aligned.m16n8k16.row.col.f32.bf16.bf16.f32 " \
                 "{%0,%1,%2,%3}, {%4,%5,%6,%7}, {%8,%9}, {%0,%1,%2,%3};" \
                 : "+f"((ac)[0]), "+f"((ac)[1]), "+f"((ac)[2]), "+f"((ac)[3]) \
                 : "r"(a0), "r"(a1), "r"(a2), "r"(a3), "r"(b0), "r"(b1))

// element (row, bf16-pair p) -> swizzled byte offset (row stride 256B)
__device__ __forceinline__ uint32_t sw_off(int row, int p) {
    return (uint32_t)row * 256u + (uint32_t)(((p >> 2) ^ (row & 7)) << 4)
         + (uint32_t)((p & 3) << 2);
}

// packed f32 pair -> bf16x2 hi + bf16x2 lo (residual), both .rn
__device__ __forceinline__ void split2(float x0, float x1,
                                       uint32_t& hi, uint32_t& lo)
{
    asm("cvt.rn.bf16x2.f32 %0, %1, %2;" : "=r"(hi) : "f"(x1), "f"(x0));
    float r0 = x0 - __uint_as_float(hi << 16);
    float r1 = x1 - __uint_as_float(hi & 0xffff0000u);
    asm("cvt.rn.bf16x2.f32 %0, %1, %2;" : "=r"(lo) : "f"(r1), "f"(r0));
}

// ---------------------------------------------------------------------------
// Threefry-2x32 (JAX partitionable) — bit-exact since R1
// ---------------------------------------------------------------------------
__device__ __forceinline__ void threefry2x32(uint32_t k0, uint32_t k1,
                                             uint32_t c0, uint32_t c1,
                                             uint32_t& y0, uint32_t& y1)
{
    uint32_t ks2 = k0 ^ k1 ^ 0x1BD11BDAu;
    uint32_t x0 = c0 + k0, x1 = c1 + k1;
#define TF_RND(r) { x0 += x1; x1 = (x1 << (r)) | (x1 >> (32 - (r))); x1 ^= x0; }
    TF_RND(13) TF_RND(15) TF_RND(26) TF_RND(6)  x0 += k1;  x1 += ks2 + 1u;
    TF_RND(17) TF_RND(29) TF_RND(16) TF_RND(24) x0 += ks2; x1 += k0  + 2u;
    TF_RND(13) TF_RND(15) TF_RND(26) TF_RND(6)  x0 += k0;  x1 += k1  + 3u;
    TF_RND(17) TF_RND(29) TF_RND(16) TF_RND(24) x0 += k1;  x1 += ks2 + 4u;
    TF_RND(13) TF_RND(15) TF_RND(26) TF_RND(6)  x0 += ks2; x1 += k0  + 5u;
#undef TF_RND
    y0 = x0; y1 = x1;
}
__device__ __forceinline__ float jax_unit_uniform(uint32_t f)
{
    uint32_t y0, y1;
    threefry2x32(0u, 42u, 0u, f, y0, y1);
    uint32_t bits = y0 ^ y1;
    float v = __uint_as_float((bits >> 9) | 0x3f800000u) - 1.0f;
    return (v == 0.0f) ? 1.17549435e-38f : v;
}

// ---------------------------------------------------------------------------
// Pre-kernel: build W1 hi/lo swizzled images + padded W2 + b1 (once per call)
// ---------------------------------------------------------------------------
__global__ void ciflow_prep(const float* __restrict__ w1,
                            const float* __restrict__ w2,
                            const float* __restrict__ b1)
{
    int i = blockIdx.x * 256 + threadIdx.x;   // 0..4607
    int n = i >> 6, p = i & 63;
    float x0 = (n < SH) ? w1[(2 * p)     * SH + n] : 0.0f;
    float x1 = (n < SH) ? w1[(2 * p + 1) * SH + n] : 0.0f;
    uint32_t hi, lo;
    split2(x0, x1, hi, lo);
    uint32_t w = sw_off(n, p) >> 2;
    gW1HI[w] = hi;
    gW1LO[w] = lo;
    if (i < 864) {
        int r = i / 12, c = i - r * 12;
        gW2P[i] = (r < SH && c < NC) ? w2[r * NC + c] : 0.0f;
    }
    if (i < 72) gB1[i] = (i < SH) ? b1[i] : 0.0f;
}

// ---------------------------------------------------------------------------
// Fused kernel: one block per graph, 512 threads, 2 CTAs/SM, HMMA A + E.
// ---------------------------------------------------------------------------
__global__ __launch_bounds__(512, 2) void ciflow_fused(
    const float* __restrict__ H,
    const int*   __restrict__ targets,
    const float* __restrict__ b2,
    const float* __restrict__ wf,  const float* __restrict__ bf,
    const float* __restrict__ p1,  const float* __restrict__ pb1,
    const float* __restrict__ p2,  const float* __restrict__ pb2,
    const float* __restrict__ ci,  const float* __restrict__ cia,
    float* __restrict__ out)
{
    extern __shared__ char smc[];
    const uint32_t sb = smem_u32(smc);

    float* b1s = (float*)(smc + B1S_B);
    float* W2p = (float*)(smc + W2P_B);
    float* Zrd = (float*)(smc + ZRED_B);

    const int g    = blockIdx.x;
    const int tid  = threadIdx.x;
    const int lane = tid & 31;
    const int wid  = tid >> 5;

    // ---- convert H + copy precomputed W images ------------------------------
    const float*  Hg  = H + (size_t)g * NPG * D;
    const float4* Hg4 = (const float4*)Hg;
    for (int i = tid; i < NPG * 32; i += 512) {            // 4000 float4
        int m = i >> 5, q = i & 31;
        float4 v = Hg4[i];
        uint32_t hi0, lo0, hi1, lo1;
        split2(v.x, v.y, hi0, lo0);
        split2(v.z, v.w, hi1, lo1);
        uint32_t o = sw_off(m, 2 * q);
        *(uint2*)(smc + HHI_B + o) = make_uint2(hi0, hi1);
        *(uint2*)(smc + HLO_B + o) = make_uint2(lo0, lo1);
    }
    for (int i = tid; i < 3 * 32; i += 512) {              // zero rows 125..127
        int m = NPG + (i >> 5), q = i & 31;
        uint32_t o = sw_off(m, 2 * q);
        *(uint2*)(smc + HHI_B + o) = make_uint2(0u, 0u);
        *(uint2*)(smc + HLO_B + o) = make_uint2(0u, 0u);
    }
    {
        const float4* s1 = (const float4*)gW1HI;
        const float4* s2 = (const float4*)gW1LO;
        float4* d1 = (float4*)(smc + WHI_B);
        float4* d2 = (float4*)(smc + WLO_B);
        for (int i = tid; i < 1152; i += 512) { d1[i] = s1[i]; d2[i] = s2[i]; }
        const float4* s3 = (const float4*)gW2P;
        float4* d3 = (float4*)(smc + W2P_B);
        for (int i = tid; i < 216; i += 512) d3[i] = s3[i];
        if (tid < 18) ((float4*)b1s)[tid] = ((const float4*)gB1)[tid];
    }
    __syncthreads();

    // ---- stage A via mma.sync: A = H @ W1t^T, 3-term bf16 compensation -----
    const int mtile = wid >> 1;
    const int half  = wid & 1;
    const int tA = lane >> 3, rA = lane & 7;
    const int mRow = mtile * 16 + ((tA & 1) << 3) + rA;
    const uint32_t aBase = sb + HHI_B + (uint32_t)mRow * 256u;
    const int aSw = mRow & 7, aCo = tA >> 1;
    const int nR4 = ((tA >> 1) << 3) + rA;
    const uint32_t b4Base = sb + WHI_B + (uint32_t)nR4 * 256u;
    const int b4Sw = rA, b4Co = tA & 1;
    const int t2 = (lane >> 3) & 1;
    const uint32_t b2Base = sb + WHI_B + (uint32_t)rA * 256u;
    const int b2Co = t2;

    float acc[5][4];
#pragma unroll
    for (int t = 0; t < 5; ++t)
#pragma unroll
        for (int c = 0; c < 4; ++c) acc[t][c] = 0.0f;

#pragma unroll 2
    for (int s = 0; s < 8; ++s) {
        const int c2 = 2 * s;
        uint32_t ah0, ah1, ah2, ah3, al0, al1, al2, al3;
        uint32_t aAddr = aBase + (uint32_t)(((c2 + aCo) ^ aSw) << 4);
        ldsm4(aAddr,         ah0, ah1, ah2, ah3);
        ldsm4(aAddr + 32768, al0, al1, al2, al3);

        if (half == 0) {
            uint32_t bh0, bh1, bh2, bh3, bl0, bl1, bl2, bl3;
            uint32_t bA = b4Base + (uint32_t)(((c2 + b4Co) ^ b4Sw) << 4);
            ldsm4(bA,         bh0, bh1, bh2, bh3);          // tiles 0,1
            ldsm4(bA + 18432, bl0, bl1, bl2, bl3);
            MMA(acc[0], ah0, ah1, ah2, ah3, bh0, bh1);
            MMA(acc[0], ah0, ah1, ah2, ah3, bl0, bl1);
            MMA(acc[0], al0, al1, al2, al3, bh0, bh1);
            MMA(acc[1], ah0, ah1, ah2, ah3, bh2, bh3);
            MMA(acc[1], ah0, ah1, ah2, ah3, bl2, bl3);
            MMA(acc[1], al0, al1, al2, al3, bh2, bh3);
            bA += 2u * 2048u;                               // tiles 2,3
            ldsm4(bA,         bh0, bh1, bh2, bh3);
            ldsm4(bA + 18432, bl0, bl1, bl2, bl3);
            MMA(acc[2], ah0, ah1, ah2, ah3, bh0, bh1);
            MMA(acc[2], ah0, ah1, ah2, ah3, bl0, bl1);
            MMA(acc[2], al0, al1, al2, al3, bh0, bh1);
            MMA(acc[3], ah0, ah1, ah2, ah3, bh2, bh3);
            MMA(acc[3], ah0, ah1, ah2, ah3, bl2, bl3);
            MMA(acc[3], al0, al1, al2, al3, bh2, bh3);
            uint32_t bB = b2Base + 4u * 2048u
                        + (uint32_t)(((c2 + b2Co) ^ rA) << 4);   // tile 4
            ldsm2(bB,         bh0, bh1);
            ldsm2(bB + 18432, bl0, bl1);
            MMA(acc[4], ah0, ah1, ah2, ah3, bh0, bh1);
            MMA(acc[4], ah0, ah1, ah2, ah3, bl0, bl1);
            MMA(acc[4], al0, al1, al2, al3, bh0, bh1);
        } else {
            uint32_t bh0, bh1, bh2, bh3, bl0, bl1, bl2, bl3;
            uint32_t bA = b4Base + 5u * 2048u
                        + (uint32_t)(((c2 + b4Co) ^ b4Sw) << 4); // tiles 5,6
            ldsm4(bA,         bh0, bh1, bh2, bh3);
            ldsm4(bA + 18432, bl0, bl1, bl2, bl3);
            MMA(acc[0], ah0, ah1, ah2, ah3, bh0, bh1);
            MMA(acc[0], ah0, ah1, ah2, ah3, bl0, bl1);
            MMA(acc[0], al0, al1, al2, al3, bh0, bh1);
            MMA(acc[1], ah0, ah1, ah2, ah3, bh2, bh3);
            MMA(acc[1], ah0, ah1, ah2, ah3, bl2, bl3);
            MMA(acc[1], al0, al1, al2, al3, bh2, bh3);
            bA += 2u * 2048u;                                // tiles 7,8
            ldsm4(bA,         bh0, bh1, bh2, bh3);
            ldsm4(bA + 18432, bl0, bl1, bl2, bl3);
            MMA(acc[2], ah0, ah1, ah2, ah3, bh0, bh1);
            MMA(acc[2], ah0, ah1, ah2, ah3, bl0, bl1);
            MMA(acc[2], al0, al1, al2, al3, bh0, bh1);
            MMA(acc[3], ah0, ah1, ah2, ah3, bh2, bh3);
            MMA(acc[3], ah0, ah1, ah2, ah3, bl2, bl3);
            MMA(acc[3], al0, al1, al2, al3, bh2, bh3);
        }
    }

    // ---- register epilogue: relu + b1, partial Z = A @ W2 -------------------
    const int nOff = 2 * (lane & 3);
    const int r0   = mtile * 16 + (lane >> 2);
    const int ntB  = half ? 5 : 0;
    const int ntC  = half ? 4 : 5;
    float z0[10], z1[10];
#pragma unroll
    for (int c = 0; c < 10; ++c) { z0[c] = 0.f; z1[c] = 0.f; }
#pragma unroll
    for (int ti = 0; ti < 5; ++ti) {
        if (ti < ntC) {
            int n = (ntB + ti) * 8 + nOff;
            float a00 = fmaxf(acc[ti][0] + b1s[n],     0.0f);
            float a01 = fmaxf(acc[ti][1] + b1s[n + 1], 0.0f);
            float a10 = fmaxf(acc[ti][2] + b1s[n],     0.0f);
            float a11 = fmaxf(acc[ti][3] + b1s[n + 1], 0.0f);
            const float* w2r0 = W2p + n * 12;
            const float* w2r1 = w2r0 + 12;
#pragma unroll
            for (int c = 0; c < 10; ++c) {
                float wa = w2r0[c], wb = w2r1[c];
                z0[c] = fmaf(a00, wa, fmaf(a01, wb, z0[c]));
                z1[c] = fmaf(a10, wa, fmaf(a11, wb, z1[c]));
            }
        }
    }
#pragma unroll
    for (int off = 1; off <= 2; off <<= 1) {
#pragma unroll
        for (int c = 0; c < 10; ++c) {
            z0[c] += __shfl_xor_sync(0xffffffffu, z0[c], off);
            z1[c] += __shfl_xor_sync(0xffffffffu, z1[c], off);
        }
    }
    __syncthreads();           // all ldmatrix reads of W region done
    if ((lane & 3) == 0) {
#pragma unroll
        for (int c = 0; c < 10; ++c) {
            Zrd[(half * 128 + r0) * 11 + c]     = z0[c];
            Zrd[(half * 128 + r0 + 8) * 11 + c] = z1[c];
        }
    }
    __syncthreads();

    // ---- Z combine + softmax -> S gmem + S^T bf16 hi/lo; others prefetch ---
    float* p1s = (float*)(smc + P1S_B);
    float* p2s = (float*)(smc + P2S_B);
    if (tid < 128) {
        int m = tid;
        const uint32_t mChunk = (uint32_t)((m >> 3) << 4);
        const uint32_t mRem   = (uint32_t)(((m >> 1) & 3) << 2)
                              + (uint32_t)((m & 1) << 1);
        if (m < NPG) {
            float z[10];
#pragma unroll
            for (int c = 0; c < 10; ++c)
                z[c] = Zrd[m * 11 + c] + Zrd[(128 + m) * 11 + c] + __ldg(&b2[c]);
            float mx = z[0];
#pragma unroll
            for (int c = 1; c < 10; ++c) mx = fmaxf(mx, z[c]);
            float ssum = 0.0f;
#pragma unroll
            for (int c = 0; c < 10; ++c) { z[c] = expf(z[c] - mx); ssum += z[c]; }
            float inv = 1.0f / ssum;
            float* gout = out + S_OFF + ((size_t)g * NPG + m) * NC;
#pragma unroll
            for (int c = 0; c < 10; ++c) z[c] *= inv;
#pragma unroll
            for (int c = 0; c < 5; ++c)
                *(float2*)(gout + 2 * c) = make_float2(z[2 * c], z[2 * c + 1]);
#pragma unroll
            for (int c = 0; c < 10; ++c) {
                __nv_bfloat16 shi = __float2bfloat16(z[c]);
                __nv_bfloat16 slo = __float2bfloat16(z[c] - __bfloat162float(shi));
                uint32_t off = (uint32_t)c * 256u
                             + ((mChunk ^ (uint32_t)((c & 7) << 4))) + mRem;
                *(unsigned short*)(smc + STHI_B + off) = __bfloat16_as_ushort(shi);
                *(unsigned short*)(smc + STLO_B + off) = __bfloat16_as_ushort(slo);
            }
        } else {
            // m = 125..127: zero K-pad columns of S^T (all 16 rows)
#pragma unroll
            for (int c = 0; c < 16; ++c) {
                uint32_t off = (uint32_t)c * 256u
                             + ((mChunk ^ (uint32_t)((c & 7) << 4))) + mRem;
                *(unsigned short*)(smc + STHI_B + off) = 0;
                *(unsigned short*)(smc + STLO_B + off) = 0;
            }
        }
    } else {
        int t = tid - 128;
        for (int i = t; i < 1024; i += 384) p1s[i] = __ldg(&p1[i]);
        if (t < 128) p2s[t] = __ldg(&p2[t]);
    }
    __syncthreads();

    // ---- stage E via mma: E = S^T @ H; per-warp 8-column d-tile -------------
    float* Es = (float*)(smc + ES_B);
    {
        const int aRow = ((tA & 1) << 3) + rA;
        const uint32_t aHiBase = sb + STHI_B + (uint32_t)aRow * 256u;
        const int aXor = aRow & 7;
        const int bOff = lane & 15;                    // H row within k-step
        uint32_t bAddr = sb + HHI_B + (uint32_t)bOff * 256u
                       + (uint32_t)((wid ^ (bOff & 7)) << 4);

        float e[4] = {0.f, 0.f, 0.f, 0.f};
#pragma unroll
        for (int s = 0; s < 8; ++s) {
            uint32_t aAddr = aHiBase + (uint32_t)(((2 * s + aCo) ^ aXor) << 4);
            uint32_t sh0, sh1, sh2, sh3, sl0, sl1, sl2, sl3;
            ldsm4(aAddr,        sh0, sh1, sh2, sh3);
            ldsm4(aAddr + 4096, sl0, sl1, sl2, sl3);   // STLO = STHI + 4096
            uint32_t bh0, bh1, bl0, bl1;
            ldsm2t(bAddr,         bh0, bh1);
            ldsm2t(bAddr + 32768, bl0, bl1);           // HLO
            MMA(e, sh0, sh1, sh2, sh3, bh0, bh1);
            MMA(e, sh0, sh1, sh2, sh3, bl0, bl1);
            MMA(e, sl0, sl1, sl2, sl3, bh0, bh1);
            bAddr += 16u * 256u;
        }
        const int c = lane >> 2;
        const int d = 8 * wid + 2 * (lane & 3);
        float* Eout = out + E_OFF + (size_t)g * (NC * D);
        *(float2*)(Es + c * D + d)   = make_float2(e[0], e[1]);
        *(float2*)(Eout + c * D + d) = make_float2(e[0], e[1]);
        if (c + 8 < NC) {
            *(float2*)(Es + (c + 8) * D + d)   = make_float2(e[2], e[3]);
            *(float2*)(Eout + (c + 8) * D + d) = make_float2(e[2], e[3]);
        }
    }
    __syncthreads();

    // ======================= fused downstream ================================
    float* ts    = (float*)(smc + TS_B);
    float* qraw  = (float*)(smc + QR_B);
    float* fms   = (float*)(smc + FMS_B);
    float* red   = (float*)(smc + RED_B);
    float* sc    = (float*)(smc + SC_B);
    float* corrs = (float*)(smc + CORR_B);
    float* cmask = (float*)(smc + CM_B);

    // epoch 1: pred1 partials
    float s0 = 0.f, s1 = 0.f;
#pragma unroll
    for (int r = 0; r < 3; ++r) {
        int i = tid + 512 * r;
        if (i < 1280) {
            float e = Es[i];
            float2 w = __ldg((const float2*)(wf + 2 * i));
            s0 = fmaf(e, w.x, s0);
            s1 = fmaf(e, w.y, s1);
        }
    }
#pragma unroll
    for (int off = 16; off; off >>= 1) {
        s0 += __shfl_down_sync(0xffffffffu, s0, off);
        s1 += __shfl_down_sync(0xffffffffu, s1, off);
    }
    if (lane == 0) { red[wid * 2] = s0; red[wid * 2 + 1] = s1; }
    __syncthreads();

    // epoch 2: sampling | correlation | Q hidden
    if (tid == 0) {
        float z0v = bf[0], z1v = bf[1];
#pragma unroll
        for (int w = 0; w < 16; ++w) { z0v += red[2 * w]; z1v += red[2 * w + 1]; }
        out[P1_OFF + g * 2 + 0] = z0v;
        out[P1_OFF + g * 2 + 1] = z1v;
        float mx = fmaxf(z0v, z1v);
        float e0 = expf(z0v - mx), e1 = expf(z1v - mx);
        float inv = 1.0f / (e0 + e1);
        float pp0 = e0 * inv, pp1 = e1 * inv;

        float u0 = jax_unit_uniform(2u * g);
        float u1 = jax_unit_uniform(2u * g + 1u);
        float l0 = logf(pp0 + 1e-12f) - logf(-logf(u0));
        float l1 = logf(pp1 + 1e-12f) - logf(-logf(u1));
        int sample = (l1 > l0) ? 1 : 0;

        out[IND_OFF + g] = (sample == targets[g]) ? 1.0f : 0.0f;
        sc[0] = pp0 + ((sample == 0) ? (1.0f - pp0) : -pp0);
        sc[1] = pp1 + ((sample == 1) ? (1.0f - pp1) : -pp1);
    }

    if (tid >= 32 && tid < 64) {
        int t = tid - 32;
        int c = t >> 4, f = t & 15;
        float a0 = __ldg(&ci[f]), a1 = __ldg(&ci[16 + f]);
        float m = fmaxf(a0, a1);
        float e0 = expf(a0 - m), e1 = expf(a1 - m);
        float colv = ((c == 0) ? e0 : e1) / (e0 + e1);
        float rm = -1e30f;
        for (int ff = 0; ff < 16; ++ff) rm = fmaxf(rm, __ldg(&cia[c * 16 + ff]));
        float rs = 0.f;
        for (int ff = 0; ff < 16; ++ff) rs += expf(__ldg(&cia[c * 16 + ff]) - rm);
        corrs[c * 16 + f] = colv * (expf(__ldg(&cia[c * 16 + f]) - rm) / rs);
    }

    if (tid >= 192) {                // Q hidden, 4-way k-split
        int t  = tid - 192;
        int u  = t >> 2, ks = t & 3;
        int c  = u >> 3, j = u & 7;
        float a = 0.0f;
        const float* ec = Es + c * 128 + 32 * ks;
        const float* pj = p1s + (32 * ks) * 8 + j;
#pragma unroll 8
        for (int k = 0; k < 32; ++k) a = fmaf(ec[k], pj[8 * k], a);
        a += __shfl_down_sync(0xffffffffu, a, 2);
        a += __shfl_down_sync(0xffffffffu, a, 1);
        if (ks == 0) ts[u] = fmaxf(a + __ldg(&pb1[j]), 0.0f);
    }
    __syncthreads();

    // epoch 3: cmask | Q output
    if (tid < 16) cmask[tid] = sc[0] * corrs[tid] + sc[1] * corrs[16 + tid];

    if (tid >= 160 && tid < 320) {
        int t = tid - 160;
        int c = t >> 4, f = t & 15;
        float a = __ldg(&pb2[f]);
#pragma unroll
        for (int j = 0; j < 8; ++j) a = fmaf(ts[c * 8 + j], p2s[j * 16 + f], a);
        qraw[t] = a;
    }
    __syncthreads();

    // epoch 4: Q softmax + feature mask
    if (tid < 160) {
        int c = tid >> 4, f = tid & 15;
        float v = qraw[tid];
        float mx = v;
#pragma unroll
        for (int off = 8; off; off >>= 1)
            mx = fmaxf(mx, __shfl_xor_sync(0xffffffffu, mx, off));
        float e = expf(v - mx);
        float ssum = e;
#pragma unroll
        for (int off = 8; off; off >>= 1)
            ssum += __shfl_xor_sync(0xffffffffu, ssum, off);
        float q = e / ssum;
        out[Q_OFF + (size_t)g * 160 + c * 16 + f] = q;
        float fm = q * cmask[f];
#pragma unroll
        for (int off = 8; off; off >>= 1)
            fm += __shfl_xor_sync(0xffffffffu, fm, off);
        if (f == 0) fms[c] = fm;
    }
    __syncthreads();

    // epoch 5: pred2
    s0 = 0.f; s1 = 0.f;
#pragma unroll
    for (int r = 0; r < 3; ++r) {
        int i = tid + 512 * r;
        if (i < 1280) {
            float e = fms[i >> 7] * Es[i];
            float2 w = __ldg((const float2*)(wf + 2 * i));
            s0 = fmaf(e, w.x, s0);
            s1 = fmaf(e, w.y, s1);
        }
    }
#pragma unroll
    for (int off = 16; off; off >>= 1) {
        s0 += __shfl_down_sync(0xffffffffu, s0, off);
        s1 += __shfl_down_sync(0xffffffffu, s1, off);
    }
    if (lane == 0) { red[wid * 2] = s0; red[wid * 2 + 1] = s1; }
    __syncthreads();
    if (tid == 0) {
        float z0v = bf[0], z1v = bf[1];
#pragma unroll
        for (int w = 0; w < 16; ++w) { z0v += red[2 * w]; z1v += red[2 * w + 1]; }
        out[P2_OFF + g * 2 + 0] = z0v;
        out[P2_OFF + g * 2 + 1] = z1v;
    }
}

// ---------------------------------------------------------------------------
extern "C" void kernel_launch(void* const* d_in, const int* in_sizes, int n_in,
                              void* d_out, int out_size)
{
    const float* H   = (const float*)d_in[0];
    const int*   tgt = (const int*)  d_in[2];
    const float* w1  = (const float*)d_in[3];
    const float* b1  = (const float*)d_in[4];
    const float* w2  = (const float*)d_in[5];
    const float* b2  = (const float*)d_in[6];
    const float* wf  = (const float*)d_in[7];
    const float* bf  = (const float*)d_in[8];
    const float* p1  = (const float*)d_in[9];
    const float* pb1 = (const float*)d_in[10];
    const float* p2  = (const float*)d_in[11];
    const float* pb2 = (const float*)d_in[12];
    const float* ci  = (const float*)d_in[13];
    const float* cia = (const float*)d_in[14];
    float* out = (float*)d_out;

    static bool attr_set = false;
    if (!attr_set) {
        cudaFuncSetAttribute(ciflow_fused,
                             cudaFuncAttributeMaxDynamicSharedMemorySize, SMEM_TOTAL);
        attr_set = true;
    }

    ciflow_prep<<<18, 256>>>(w1, w2, b1);
    ciflow_fused<<<NGRAPH, 512, SMEM_TOTAL>>>(H, tgt, b2, wf, bf,
                                              p1, pb1, p2, pb2, ci, cia, out);
}